// round 1
// baseline (speedup 1.0000x reference)
#include <cuda_runtime.h>

#define B_  4
#define S_  2048
#define D_  1024
#define H_  16
#define DH_ 64
#define M_  (B_ * S_)   // 8192

// Scratch for Q/K/V in [B, H, S, DH] layout (device globals: no allocation).
__device__ float g_q[B_ * H_ * S_ * DH_];
__device__ float g_k[B_ * H_ * S_ * DH_];
__device__ float g_v[B_ * H_ * S_ * DH_];

// ---------------------------------------------------------------------------
// Kernel 1: QKV projection GEMM.  C[m,n] = sum_k X[m,k] * W[k,n]
// M=8192, N=1024, K=1024.  blockIdx.z selects {Wq->g_q, Wk->g_k, Wv->g_v}.
// Classic 128x128x8 tile, 256 threads, 8x8 register microtile.
// Epilogue writes into [B,H,S,DH] layout.
// ---------------------------------------------------------------------------
__global__ __launch_bounds__(256, 2) void qkv_gemm(
    const float* __restrict__ X,
    const float* __restrict__ Wq,
    const float* __restrict__ Wk,
    const float* __restrict__ Wv)
{
    constexpr int BM = 128, BN = 128, BK = 8, TM = 8, TN = 8;
    __shared__ float As[BK][BM];   // transposed A tile
    __shared__ float Bs[BK][BN];

    const float* W = (blockIdx.z == 0) ? Wq : (blockIdx.z == 1) ? Wk : Wv;
    float*       C = (blockIdx.z == 0) ? g_q : (blockIdx.z == 1) ? g_k : g_v;

    const int tid  = threadIdx.x;
    const int brow = blockIdx.y;           // M tile index (0..63)
    const int bcol = blockIdx.x;           // N tile index (0..7)
    const int tr   = tid / 16;             // 0..15
    const int tc   = tid % 16;             // 0..15

    // global-load coordinates
    const int aRow = tid >> 1;             // 0..127
    const int aCol = (tid & 1) * 4;        // 0 or 4
    const int bRow = tid >> 5;             // 0..7
    const int bCol = (tid & 31) * 4;       // 0..124

    const float* Aptr = X + (size_t)(brow * BM) * D_;
    const float* Bptr = W + bcol * BN;

    float acc[TM][TN];
    #pragma unroll
    for (int i = 0; i < TM; i++)
        #pragma unroll
        for (int j = 0; j < TN; j++) acc[i][j] = 0.f;

    float regM[TM], regN[TN];

    for (int kt = 0; kt < D_; kt += BK) {
        float4 a4 = *(const float4*)(Aptr + (size_t)aRow * D_ + kt + aCol);
        As[aCol + 0][aRow] = a4.x;
        As[aCol + 1][aRow] = a4.y;
        As[aCol + 2][aRow] = a4.z;
        As[aCol + 3][aRow] = a4.w;
        float4 b4 = *(const float4*)(Bptr + (size_t)(kt + bRow) * D_ + bCol);
        *(float4*)&Bs[bRow][bCol] = b4;
        __syncthreads();

        #pragma unroll
        for (int k = 0; k < BK; k++) {
            #pragma unroll
            for (int i = 0; i < TM; i += 4) {
                float4 t = *(const float4*)&As[k][tr * TM + i];
                regM[i] = t.x; regM[i+1] = t.y; regM[i+2] = t.z; regM[i+3] = t.w;
            }
            #pragma unroll
            for (int j = 0; j < TN; j += 4) {
                float4 t = *(const float4*)&Bs[k][tc * TN + j];
                regN[j] = t.x; regN[j+1] = t.y; regN[j+2] = t.z; regN[j+3] = t.w;
            }
            #pragma unroll
            for (int i = 0; i < TM; i++)
                #pragma unroll
                for (int j = 0; j < TN; j++)
                    acc[i][j] = fmaf(regM[i], regN[j], acc[i][j]);
        }
        __syncthreads();
    }

    // Epilogue: write into [B, H, S, DH] layout.
    #pragma unroll
    for (int i = 0; i < TM; i++) {
        const int m = brow * BM + tr * TM + i;
        const int b = m >> 11;             // / S_
        const int s = m & (S_ - 1);
        #pragma unroll
        for (int j = 0; j < TN; j += 4) {
            const int n  = bcol * BN + tc * TN + j;
            const int h  = n >> 6;         // / DH_
            const int dh = n & (DH_ - 1);
            float4 o4 = make_float4(acc[i][j], acc[i][j+1], acc[i][j+2], acc[i][j+3]);
            *(float4*)&C[(((size_t)(b * H_ + h) * S_ + s) * DH_) + dh] = o4;
        }
    }
}

// ---------------------------------------------------------------------------
// Kernel 2: flash-style attention.  One query row per thread.
// Block = 128 threads -> 128 query rows; grid = (S/128, H, B).
// K/V streamed through smem in tiles of AK=16 rows; softmax is thread-local.
// ---------------------------------------------------------------------------
__global__ __launch_bounds__(128) void attn_kernel(float* __restrict__ out)
{
    constexpr int AK = 16;
    __shared__ float ks[AK * DH_];
    __shared__ float vs[AK * DH_];

    const int b   = blockIdx.z;
    const int h   = blockIdx.y;
    const int tid = threadIdx.x;
    const int qi  = blockIdx.x * 128 + tid;

    const size_t base = (size_t)(b * H_ + h) * S_ * DH_;
    const float* qp = g_q + base + (size_t)qi * DH_;
    const float* kb = g_k + base;
    const float* vb = g_v + base;

    float qr[DH_], o[DH_];
    #pragma unroll
    for (int d = 0; d < DH_; d += 4) {
        float4 t = *(const float4*)(qp + d);
        qr[d] = t.x; qr[d+1] = t.y; qr[d+2] = t.z; qr[d+3] = t.w;
    }
    #pragma unroll
    for (int d = 0; d < DH_; d++) o[d] = 0.f;

    float mrow = -1e30f;
    float l    = 0.f;

    for (int kt = 0; kt < S_; kt += AK) {
        __syncthreads();
        // tile = 16 rows x 64 floats = 256 float4; 128 threads x 2 each. Contiguous copy.
        const float4* ksrc = (const float4*)(kb + (size_t)kt * DH_);
        const float4* vsrc = (const float4*)(vb + (size_t)kt * DH_);
        ((float4*)ks)[tid]       = ksrc[tid];
        ((float4*)ks)[tid + 128] = ksrc[tid + 128];
        ((float4*)vs)[tid]       = vsrc[tid];
        ((float4*)vs)[tid + 128] = vsrc[tid + 128];
        __syncthreads();

        // scores for this thread's query row against 16 keys
        float s[AK];
        #pragma unroll
        for (int j = 0; j < AK; j++) {
            float acc = 0.f;
            #pragma unroll
            for (int d = 0; d < DH_; d += 4) {
                float4 kk = *(const float4*)&ks[j * DH_ + d];
                acc = fmaf(qr[d],     kk.x, acc);
                acc = fmaf(qr[d + 1], kk.y, acc);
                acc = fmaf(qr[d + 2], kk.z, acc);
                acc = fmaf(qr[d + 3], kk.w, acc);
            }
            s[j] = acc * 0.0625f;   // / n_heads = /16 (per reference)
        }

        // online softmax (thread-local: this thread owns the whole row)
        float mt = mrow;
        #pragma unroll
        for (int j = 0; j < AK; j++) mt = fmaxf(mt, s[j]);
        const float scale = __expf(mrow - mt);
        mrow = mt;
        float ls = 0.f;
        #pragma unroll
        for (int j = 0; j < AK; j++) { s[j] = __expf(s[j] - mt); ls += s[j]; }
        l = l * scale + ls;

        #pragma unroll
        for (int d = 0; d < DH_; d++) o[d] *= scale;

        // O += P * V
        #pragma unroll
        for (int j = 0; j < AK; j++) {
            const float p = s[j];
            #pragma unroll
            for (int d = 0; d < DH_; d += 4) {
                float4 vv = *(const float4*)&vs[j * DH_ + d];
                o[d]     = fmaf(p, vv.x, o[d]);
                o[d + 1] = fmaf(p, vv.y, o[d + 1]);
                o[d + 2] = fmaf(p, vv.z, o[d + 2]);
                o[d + 3] = fmaf(p, vv.w, o[d + 3]);
            }
        }
    }

    const float inv = __fdividef(1.f, l);
    float* op = out + ((size_t)b * S_ + qi) * D_ + h * DH_;
    #pragma unroll
    for (int d = 0; d < DH_; d += 4) {
        float4 t = make_float4(o[d] * inv, o[d+1] * inv, o[d+2] * inv, o[d+3] * inv);
        *(float4*)(op + d) = t;
    }
}

// ---------------------------------------------------------------------------
// Launch
// ---------------------------------------------------------------------------
extern "C" void kernel_launch(void* const* d_in, const int* in_sizes, int n_in,
                              void* d_out, int out_size)
{
    const float* x  = (const float*)d_in[0];
    const float* wq = (const float*)d_in[1];
    const float* wk = (const float*)d_in[2];
    const float* wv = (const float*)d_in[3];
    float* out = (float*)d_out;

    dim3 g1(D_ / 128, M_ / 128, 3);   // (8, 64, 3)
    qkv_gemm<<<g1, 256>>>(x, wq, wk, wv);

    dim3 g2(S_ / 128, H_, B_);        // (16, 16, 4)
    attn_kernel<<<g2, 128>>>(out);
}

// round 3
// speedup vs baseline: 1.2702x; 1.2702x over previous
#include <cuda_runtime.h>
#include <cuda_bf16.h>
#include <cstdint>

#define B_  4
#define S_  2048
#define D_  1024
#define H_  16
#define DH_ 64
#define M_  (B_ * S_)   // 8192

// ---------------- device scratch (no allocations allowed) -------------------
__device__ float g_q[B_ * H_ * S_ * DH_];
__device__ float g_k[B_ * H_ * S_ * DH_];
__device__ float g_v[B_ * H_ * S_ * DH_];
__device__ __nv_bfloat16 g_xh[M_ * D_];
__device__ __nv_bfloat16 g_xl[M_ * D_];
__device__ __nv_bfloat16 g_wth[3 * D_ * D_];   // W^T split hi: [z][n][k]
__device__ __nv_bfloat16 g_wtl[3 * D_ * D_];   // W^T split lo

// ---------------- helpers ----------------------------------------------------
static __device__ __forceinline__ uint32_t s2u(const void* p) {
    uint32_t a;
    asm("{ .reg .u64 t; cvta.to.shared.u64 t, %1; cvt.u32.u64 %0, t; }"
        : "=r"(a) : "l"(p));
    return a;
}

static __device__ __forceinline__ void cp16(uint32_t s, const void* g) {
    asm volatile("cp.async.cg.shared.global [%0], [%1], 16;"
                 :: "r"(s), "l"(__cvta_generic_to_global(g)));
}

#define LDSM4(r0, r1, r2, r3, a)                                            \
    asm volatile("ldmatrix.sync.aligned.m8n8.x4.shared.b16 "                \
                 "{%0,%1,%2,%3}, [%4];"                                     \
                 : "=r"(r0), "=r"(r1), "=r"(r2), "=r"(r3) : "r"(a))

#define MMA16816(d, a, b0v, b1v)                                            \
    asm volatile("mma.sync.aligned.m16n8k16.row.col.f32.bf16.bf16.f32 "     \
                 "{%0,%1,%2,%3}, {%4,%5,%6,%7}, {%8,%9}, {%0,%1,%2,%3};"    \
                 : "+f"((d)[0]), "+f"((d)[1]), "+f"((d)[2]), "+f"((d)[3])   \
                 : "r"((a)[0]), "r"((a)[1]), "r"((a)[2]), "r"((a)[3]),      \
                   "r"(b0v), "r"(b1v))

static __device__ __forceinline__ void bsplit(float v, __nv_bfloat16& h, __nv_bfloat16& l) {
    h = __float2bfloat16(v);
    l = __float2bfloat16(v - __bfloat162float(h));
}

// ---------------------------------------------------------------------------
// Preprocessing: split X into bf16 hi/lo
// ---------------------------------------------------------------------------
__global__ void xsplit(const float* __restrict__ x)
{
    int i = blockIdx.x * 256 + threadIdx.x;   // float4 index
    float4 v = ((const float4*)x)[i];
    __nv_bfloat16 h0, h1, h2, h3, l0, l1, l2, l3;
    bsplit(v.x, h0, l0); bsplit(v.y, h1, l1);
    bsplit(v.z, h2, l2); bsplit(v.w, h3, l3);
    __nv_bfloat162* ph = (__nv_bfloat162*)g_xh;
    __nv_bfloat162* pl = (__nv_bfloat162*)g_xl;
    ph[2 * i]     = __nv_bfloat162(h0, h1);
    ph[2 * i + 1] = __nv_bfloat162(h2, h3);
    pl[2 * i]     = __nv_bfloat162(l0, l1);
    pl[2 * i + 1] = __nv_bfloat162(l2, l3);
}

// ---------------------------------------------------------------------------
// Preprocessing: transpose + split W -> Wt[z][n][k] bf16 hi/lo
// ---------------------------------------------------------------------------
__global__ void wsplit(const float* __restrict__ Wq,
                       const float* __restrict__ Wk,
                       const float* __restrict__ Wv)
{
    __shared__ float t[32][33];
    const int z = blockIdx.z;
    const float* W = (z == 0) ? Wq : (z == 1) ? Wk : Wv;
    const int n  = blockIdx.x * 32 + threadIdx.x;
    const int k0 = blockIdx.y * 32;
    #pragma unroll
    for (int dy = 0; dy < 32; dy += 8) {
        int k = k0 + threadIdx.y + dy;
        t[threadIdx.y + dy][threadIdx.x] = W[(size_t)k * D_ + n];
    }
    __syncthreads();
    const int kk = k0 + threadIdx.x;
    #pragma unroll
    for (int dy = 0; dy < 32; dy += 8) {
        int nn = blockIdx.x * 32 + threadIdx.y + dy;
        float v = t[threadIdx.x][threadIdx.y + dy];
        __nv_bfloat16 hi, lo;
        bsplit(v, hi, lo);
        size_t o = (size_t)z * D_ * D_ + (size_t)nn * D_ + kk;
        g_wth[o] = hi;
        g_wtl[o] = lo;
    }
}

// ---------------------------------------------------------------------------
// QKV GEMM via mma.sync bf16, 3-term split.  C[m,n] = sum_k X[m,k] W[k,n]
// CTA tile 128x128, BK=32, 3 cp.async stages, 256 thr (8 warps = 2Mx4N of 64x32)
// Smem stage layout: A tile then B tile, each 128 rows x 128B
//   row r: [hi k0..31 (4x16B)][lo k0..31 (4x16B)], 16B-chunk swizzled by r&7.
// ---------------------------------------------------------------------------
#define BK    32
#define NK    (D_ / BK)          // 32
#define NSTG  3
#define TILEB 16384              // 128 x 128B
#define STGB  (2 * TILEB)        // A + B
#define SMEM_G (NSTG * STGB)     // 98304

static __device__ __forceinline__ void load_stage(
    uint32_t sb, int st, int kb, int tid,
    const __nv_bfloat16* Ah, const __nv_bfloat16* Al,
    const __nv_bfloat16* Bh, const __nv_bfloat16* Bl)
{
    const uint32_t aBase = sb + st * STGB;
    const uint32_t bBase = aBase + TILEB;
    #pragma unroll
    for (int j = 0; j < 4; j++) {
        int idx = tid + j * 256;           // 0..1023
        int r = idx >> 3;                  // row (m for A, n for B)
        int c = idx & 7;                   // chunk slot: 0-3 hi, 4-7 lo
        uint32_t so = (uint32_t)((c ^ (r & 7)) << 4) + (uint32_t)(r * 128);
        size_t go = (size_t)r * D_ + kb + (c & 3) * 8;
        cp16(aBase + so, (c < 4 ? Ah : Al) + go);
        cp16(bBase + so, (c < 4 ? Bh : Bl) + go);
    }
}

__global__ __launch_bounds__(256) void qkv_gemm_mma()
{
    extern __shared__ char smem[];
    const uint32_t sb = s2u(smem);
    const int tid  = threadIdx.x;
    const int warp = tid >> 5;
    const int lane = tid & 31;
    const int wm   = warp & 1;             // 0..1
    const int wn   = warp >> 1;            // 0..3

    const int n0 = blockIdx.x * 128;
    const int m0 = blockIdx.y * 128;
    const int z  = blockIdx.z;

    const __nv_bfloat16* Ah = g_xh + (size_t)m0 * D_;
    const __nv_bfloat16* Al = g_xl + (size_t)m0 * D_;
    const __nv_bfloat16* Bh = g_wth + (size_t)z * D_ * D_ + (size_t)n0 * D_;
    const __nv_bfloat16* Bl = g_wtl + (size_t)z * D_ * D_ + (size_t)n0 * D_;

    float acc[4][4][4];
    #pragma unroll
    for (int mi = 0; mi < 4; mi++)
        #pragma unroll
        for (int ni = 0; ni < 4; ni++)
            #pragma unroll
            for (int r = 0; r < 4; r++) acc[mi][ni][r] = 0.f;

    // ldmatrix row/offset precompute.
    // A x4: m = wm*64 + mi*16 + (lane&15); k-granule = g0 + (lane>>4)
    int aRow[4];
    #pragma unroll
    for (int mi = 0; mi < 4; mi++) aRow[mi] = wm * 64 + mi * 16 + (lane & 15);
    const int aG = (lane >> 4);            // 0/1 added to g0
    // B x4 (pair): n = wn*32 + pair*16 + (lane&7) + ((lane&16)>>1); g = g0 + ((lane>>3)&1)
    int bRow[2];
    #pragma unroll
    for (int p = 0; p < 2; p++) bRow[p] = wn * 32 + p * 16 + (lane & 7) + ((lane & 16) >> 1);
    const int bG = (lane >> 3) & 1;

    // prologue
    #pragma unroll
    for (int s = 0; s < NSTG; s++) {
        load_stage(sb, s, s * BK, tid, Ah, Al, Bh, Bl);
        asm volatile("cp.async.commit_group;" ::: "memory");
    }

    for (int i = 0; i < NK; i++) {
        asm volatile("cp.async.wait_group 2;" ::: "memory");
        __syncthreads();

        const uint32_t aBase = sb + (i % NSTG) * STGB;
        const uint32_t bBase = aBase + TILEB;

        #pragma unroll
        for (int kstep = 0; kstep < 2; kstep++) {
            const int g0 = kstep * 2;

            uint32_t ah[4][4], bh[2][4];
            #pragma unroll
            for (int mi = 0; mi < 4; mi++) {
                int r = aRow[mi];
                uint32_t ad = aBase + r * 128 + (((g0 + aG) ^ (r & 7)) << 4);
                LDSM4(ah[mi][0], ah[mi][1], ah[mi][2], ah[mi][3], ad);
            }
            #pragma unroll
            for (int p = 0; p < 2; p++) {
                int r = bRow[p];
                uint32_t bd = bBase + r * 128 + (((g0 + bG) ^ (r & 7)) << 4);
                LDSM4(bh[p][0], bh[p][1], bh[p][2], bh[p][3], bd);
            }
            #pragma unroll
            for (int mi = 0; mi < 4; mi++)
                #pragma unroll
                for (int ni = 0; ni < 4; ni++)
                    MMA16816(acc[mi][ni], ah[mi], bh[ni >> 1][(ni & 1) * 2], bh[ni >> 1][(ni & 1) * 2 + 1]);

            // term 2: Ah * Bl   (lo chunks: slot = 4 + g)
            {
                uint32_t bl[2][4];
                #pragma unroll
                for (int p = 0; p < 2; p++) {
                    int r = bRow[p];
                    uint32_t bd = bBase + r * 128 + ((((4 + g0 + bG)) ^ (r & 7)) << 4);
                    LDSM4(bl[p][0], bl[p][1], bl[p][2], bl[p][3], bd);
                }
                #pragma unroll
                for (int mi = 0; mi < 4; mi++)
                    #pragma unroll
                    for (int ni = 0; ni < 4; ni++)
                        MMA16816(acc[mi][ni], ah[mi], bl[ni >> 1][(ni & 1) * 2], bl[ni >> 1][(ni & 1) * 2 + 1]);
            }
            // term 3: Al * Bh
            {
                uint32_t al[4][4];
                #pragma unroll
                for (int mi = 0; mi < 4; mi++) {
                    int r = aRow[mi];
                    uint32_t ad = aBase + r * 128 + ((((4 + g0 + aG)) ^ (r & 7)) << 4);
                    LDSM4(al[mi][0], al[mi][1], al[mi][2], al[mi][3], ad);
                }
                #pragma unroll
                for (int mi = 0; mi < 4; mi++)
                    #pragma unroll
                    for (int ni = 0; ni < 4; ni++)
                        MMA16816(acc[mi][ni], al[mi], bh[ni >> 1][(ni & 1) * 2], bh[ni >> 1][(ni & 1) * 2 + 1]);
            }
        }

        __syncthreads();
        int nx = i + NSTG;
        if (nx < NK) load_stage(sb, i % NSTG, nx * BK, tid, Ah, Al, Bh, Bl);
        asm volatile("cp.async.commit_group;" ::: "memory");
    }

    // epilogue -> C in [B,H,S,DH]
    float* C = (z == 0) ? g_q : (z == 1) ? g_k : g_v;
    #pragma unroll
    for (int mi = 0; mi < 4; mi++) {
        #pragma unroll
        for (int ni = 0; ni < 4; ni++) {
            int m = m0 + wm * 64 + mi * 16 + (lane >> 2);
            int n = n0 + wn * 32 + ni * 8 + ((lane & 3) << 1);
            int h  = n >> 6;
            int dh = n & (DH_ - 1);
            #pragma unroll
            for (int half = 0; half < 2; half++) {
                int mm = m + half * 8;
                int b  = mm >> 11;
                int s  = mm & (S_ - 1);
                float2 v = make_float2(acc[mi][ni][half * 2], acc[mi][ni][half * 2 + 1]);
                *(float2*)&C[(((size_t)(b * H_ + h) * S_ + s) * DH_) + dh] = v;
            }
        }
    }
}

// ---------------------------------------------------------------------------
// Kernel 2: flash-style attention (unchanged; LDS-bound per round-1 ncu).
// ---------------------------------------------------------------------------
__global__ __launch_bounds__(128) void attn_kernel(float* __restrict__ out)
{
    constexpr int AK = 16;
    __shared__ float ks[AK * DH_];
    __shared__ float vs[AK * DH_];

    const int b   = blockIdx.z;
    const int h   = blockIdx.y;
    const int tid = threadIdx.x;
    const int qi  = blockIdx.x * 128 + tid;

    const size_t base = (size_t)(b * H_ + h) * S_ * DH_;
    const float* qp = g_q + base + (size_t)qi * DH_;
    const float* kb = g_k + base;
    const float* vb = g_v + base;

    float qr[DH_], o[DH_];
    #pragma unroll
    for (int d = 0; d < DH_; d += 4) {
        float4 t = *(const float4*)(qp + d);
        qr[d] = t.x; qr[d+1] = t.y; qr[d+2] = t.z; qr[d+3] = t.w;
    }
    #pragma unroll
    for (int d = 0; d < DH_; d++) o[d] = 0.f;

    float mrow = -1e30f;
    float l    = 0.f;

    for (int kt = 0; kt < S_; kt += AK) {
        __syncthreads();
        const float4* ksrc = (const float4*)(kb + (size_t)kt * DH_);
        const float4* vsrc = (const float4*)(vb + (size_t)kt * DH_);
        ((float4*)ks)[tid]       = ksrc[tid];
        ((float4*)ks)[tid + 128] = ksrc[tid + 128];
        ((float4*)vs)[tid]       = vsrc[tid];
        ((float4*)vs)[tid + 128] = vsrc[tid + 128];
        __syncthreads();

        float s[AK];
        #pragma unroll
        for (int j = 0; j < AK; j++) {
            float acc = 0.f;
            #pragma unroll
            for (int d = 0; d < DH_; d += 4) {
                float4 kk = *(const float4*)&ks[j * DH_ + d];
                acc = fmaf(qr[d],     kk.x, acc);
                acc = fmaf(qr[d + 1], kk.y, acc);
                acc = fmaf(qr[d + 2], kk.z, acc);
                acc = fmaf(qr[d + 3], kk.w, acc);
            }
            s[j] = acc * 0.0625f;
        }

        float mt = mrow;
        #pragma unroll
        for (int j = 0; j < AK; j++) mt = fmaxf(mt, s[j]);
        const float scale = __expf(mrow - mt);
        mrow = mt;
        float ls = 0.f;
        #pragma unroll
        for (int j = 0; j < AK; j++) { s[j] = __expf(s[j] - mt); ls += s[j]; }
        l = l * scale + ls;

        #pragma unroll
        for (int d = 0; d < DH_; d++) o[d] *= scale;

        #pragma unroll
        for (int j = 0; j < AK; j++) {
            const float p = s[j];
            #pragma unroll
            for (int d = 0; d < DH_; d += 4) {
                float4 vv = *(const float4*)&vs[j * DH_ + d];
                o[d]     = fmaf(p, vv.x, o[d]);
                o[d + 1] = fmaf(p, vv.y, o[d + 1]);
                o[d + 2] = fmaf(p, vv.z, o[d + 2]);
                o[d + 3] = fmaf(p, vv.w, o[d + 3]);
            }
        }
    }

    const float inv = __fdividef(1.f, l);
    float* op = out + ((size_t)b * S_ + qi) * D_ + h * DH_;
    #pragma unroll
    for (int d = 0; d < DH_; d += 4) {
        float4 t = make_float4(o[d] * inv, o[d+1] * inv, o[d+2] * inv, o[d+3] * inv);
        *(float4*)(op + d) = t;
    }
}

// ---------------------------------------------------------------------------
// Launch
// ---------------------------------------------------------------------------
extern "C" void kernel_launch(void* const* d_in, const int* in_sizes, int n_in,
                              void* d_out, int out_size)
{
    const float* x  = (const float*)d_in[0];
    const float* wq = (const float*)d_in[1];
    const float* wk = (const float*)d_in[2];
    const float* wv = (const float*)d_in[3];
    float* out = (float*)d_out;

    static bool attr_set = false;
    if (!attr_set) {
        cudaFuncSetAttribute(qkv_gemm_mma,
                             cudaFuncAttributeMaxDynamicSharedMemorySize, SMEM_G);
        attr_set = true;
    }

    xsplit<<<(M_ * D_ / 4) / 256, 256>>>(x);
    wsplit<<<dim3(32, 32, 3), dim3(32, 8)>>>(wq, wk, wv);
    qkv_gemm_mma<<<dim3(D_ / 128, M_ / 128, 3), 256, SMEM_G>>>();

    attn_kernel<<<dim3(S_ / 128, H_, B_), 128>>>(out);
}

// round 4
// speedup vs baseline: 3.3214x; 2.6148x over previous
#include <cuda_runtime.h>
#include <cuda_bf16.h>
#include <cstdint>

#define B_  4
#define S_  2048
#define D_  1024
#define H_  16
#define DH_ 64
#define M_  (B_ * S_)   // 8192

// ---------------- device scratch (no allocations allowed) -------------------
__device__ float g_v[B_ * H_ * S_ * DH_];                 // V fp32 [b,h][s][dh]
__device__ __nv_bfloat16 g_xh[M_ * D_];
__device__ __nv_bfloat16 g_xl[M_ * D_];
__device__ __nv_bfloat16 g_wth[3 * D_ * D_];
__device__ __nv_bfloat16 g_wtl[3 * D_ * D_];
__device__ __nv_bfloat16 g_qh[B_ * H_ * S_ * DH_];        // Q hi [b,h][s][dh]
__device__ __nv_bfloat16 g_ql[B_ * H_ * S_ * DH_];
__device__ __nv_bfloat16 g_kh[B_ * H_ * S_ * DH_];
__device__ __nv_bfloat16 g_kl[B_ * H_ * S_ * DH_];
__device__ __nv_bfloat16 g_vth[B_ * H_ * DH_ * S_];       // V^T hi [b,h][dh][s]
__device__ __nv_bfloat16 g_vtl[B_ * H_ * DH_ * S_];

// ---------------- helpers ----------------------------------------------------
static __device__ __forceinline__ uint32_t s2u(const void* p) {
    uint32_t a;
    asm("{ .reg .u64 t; cvta.to.shared.u64 t, %1; cvt.u32.u64 %0, t; }"
        : "=r"(a) : "l"(p));
    return a;
}

static __device__ __forceinline__ void cp16(uint32_t s, const void* g) {
    asm volatile("cp.async.cg.shared.global [%0], [%1], 16;"
                 :: "r"(s), "l"(__cvta_generic_to_global(g)));
}

#define LDSM4(r0, r1, r2, r3, a)                                            \
    asm volatile("ldmatrix.sync.aligned.m8n8.x4.shared.b16 "                \
                 "{%0,%1,%2,%3}, [%4];"                                     \
                 : "=r"(r0), "=r"(r1), "=r"(r2), "=r"(r3) : "r"(a))

#define MMA16816(d, a, b0v, b1v)                                            \
    asm volatile("mma.sync.aligned.m16n8k16.row.col.f32.bf16.bf16.f32 "     \
                 "{%0,%1,%2,%3}, {%4,%5,%6,%7}, {%8,%9}, {%0,%1,%2,%3};"    \
                 : "+f"((d)[0]), "+f"((d)[1]), "+f"((d)[2]), "+f"((d)[3])   \
                 : "r"((a)[0]), "r"((a)[1]), "r"((a)[2]), "r"((a)[3]),      \
                   "r"(b0v), "r"(b1v))

static __device__ __forceinline__ void bsplit(float v, __nv_bfloat16& h, __nv_bfloat16& l) {
    h = __float2bfloat16(v);
    l = __float2bfloat16(v - __bfloat162float(h));
}

// pack two fp32 into bf16x2 hi and lo halves (split precision)
static __device__ __forceinline__ void split2(float a, float b, uint32_t& hi, uint32_t& lo) {
    __nv_bfloat16 ha = __float2bfloat16(a), hb = __float2bfloat16(b);
    __nv_bfloat16 la = __float2bfloat16(a - __bfloat162float(ha));
    __nv_bfloat16 lb = __float2bfloat16(b - __bfloat162float(hb));
    hi = (uint32_t)__bfloat16_as_ushort(ha) | ((uint32_t)__bfloat16_as_ushort(hb) << 16);
    lo = (uint32_t)__bfloat16_as_ushort(la) | ((uint32_t)__bfloat16_as_ushort(lb) << 16);
}

// FFMA-only exp (no MUFU): exp(x) for x <= ~0, clamped at -87.
static __device__ __forceinline__ float fexp(float x) {
    x = fmaxf(x, -87.0f);
    float t = x * 1.4426950408889634f;
    float n = t + 12582912.0f;                       // round-to-nearest-int trick
    int   e = __float_as_int(n) - 0x4B400000;        // integer part
    float fn = n - 12582912.0f;
    float f  = t - fn;                               // f in [-0.5, 0.5]
    float p = 0.0013333558f;
    p = fmaf(p, f, 0.0096181291f);
    p = fmaf(p, f, 0.0555041087f);
    p = fmaf(p, f, 0.2402265069f);
    p = fmaf(p, f, 0.6931471806f);
    p = fmaf(p, f, 1.0f);
    return p * __int_as_float((e + 127) << 23);
}

// ---------------------------------------------------------------------------
// Preprocessing: split X into bf16 hi/lo
// ---------------------------------------------------------------------------
__global__ void xsplit(const float* __restrict__ x)
{
    int i = blockIdx.x * 256 + threadIdx.x;   // float4 index
    float4 v = ((const float4*)x)[i];
    __nv_bfloat16 h0, h1, h2, h3, l0, l1, l2, l3;
    bsplit(v.x, h0, l0); bsplit(v.y, h1, l1);
    bsplit(v.z, h2, l2); bsplit(v.w, h3, l3);
    __nv_bfloat162* ph = (__nv_bfloat162*)g_xh;
    __nv_bfloat162* pl = (__nv_bfloat162*)g_xl;
    ph[2 * i]     = __nv_bfloat162(h0, h1);
    ph[2 * i + 1] = __nv_bfloat162(h2, h3);
    pl[2 * i]     = __nv_bfloat162(l0, l1);
    pl[2 * i + 1] = __nv_bfloat162(l2, l3);
}

// ---------------------------------------------------------------------------
// Preprocessing: transpose + split W -> Wt[z][n][k] bf16 hi/lo
// ---------------------------------------------------------------------------
__global__ void wsplit(const float* __restrict__ Wq,
                       const float* __restrict__ Wk,
                       const float* __restrict__ Wv)
{
    __shared__ float t[32][33];
    const int z = blockIdx.z;
    const float* W = (z == 0) ? Wq : (z == 1) ? Wk : Wv;
    const int n  = blockIdx.x * 32 + threadIdx.x;
    const int k0 = blockIdx.y * 32;
    #pragma unroll
    for (int dy = 0; dy < 32; dy += 8) {
        int k = k0 + threadIdx.y + dy;
        t[threadIdx.y + dy][threadIdx.x] = W[(size_t)k * D_ + n];
    }
    __syncthreads();
    const int kk = k0 + threadIdx.x;
    #pragma unroll
    for (int dy = 0; dy < 32; dy += 8) {
        int nn = blockIdx.x * 32 + threadIdx.y + dy;
        float v = t[threadIdx.x][threadIdx.y + dy];
        __nv_bfloat16 hi, lo;
        bsplit(v, hi, lo);
        size_t o = (size_t)z * D_ * D_ + (size_t)nn * D_ + kk;
        g_wth[o] = hi;
        g_wtl[o] = lo;
    }
}

// ---------------------------------------------------------------------------
// QKV GEMM via mma.sync bf16, 3-term split (round-3 core, new epilogue).
// ---------------------------------------------------------------------------
#define BK    32
#define NK    (D_ / BK)          // 32
#define NSTG  3
#define TILEB 16384              // 128 x 128B
#define STGB  (2 * TILEB)        // A + B
#define SMEM_G (NSTG * STGB)     // 98304

static __device__ __forceinline__ void load_stage(
    uint32_t sb, int st, int kb, int tid,
    const __nv_bfloat16* Ah, const __nv_bfloat16* Al,
    const __nv_bfloat16* Bh, const __nv_bfloat16* Bl)
{
    const uint32_t aBase = sb + st * STGB;
    const uint32_t bBase = aBase + TILEB;
    #pragma unroll
    for (int j = 0; j < 4; j++) {
        int idx = tid + j * 256;           // 0..1023
        int r = idx >> 3;
        int c = idx & 7;
        uint32_t so = (uint32_t)((c ^ (r & 7)) << 4) + (uint32_t)(r * 128);
        size_t go = (size_t)r * D_ + kb + (c & 3) * 8;
        cp16(aBase + so, (c < 4 ? Ah : Al) + go);
        cp16(bBase + so, (c < 4 ? Bh : Bl) + go);
    }
}

__global__ __launch_bounds__(256) void qkv_gemm_mma()
{
    extern __shared__ char smem[];
    const uint32_t sb = s2u(smem);
    const int tid  = threadIdx.x;
    const int warp = tid >> 5;
    const int lane = tid & 31;
    const int wm   = warp & 1;
    const int wn   = warp >> 1;

    const int n0 = blockIdx.x * 128;
    const int m0 = blockIdx.y * 128;
    const int z  = blockIdx.z;

    const __nv_bfloat16* Ah = g_xh + (size_t)m0 * D_;
    const __nv_bfloat16* Al = g_xl + (size_t)m0 * D_;
    const __nv_bfloat16* Bh = g_wth + (size_t)z * D_ * D_ + (size_t)n0 * D_;
    const __nv_bfloat16* Bl = g_wtl + (size_t)z * D_ * D_ + (size_t)n0 * D_;

    float acc[4][4][4];
    #pragma unroll
    for (int mi = 0; mi < 4; mi++)
        #pragma unroll
        for (int ni = 0; ni < 4; ni++)
            #pragma unroll
            for (int r = 0; r < 4; r++) acc[mi][ni][r] = 0.f;

    int aRow[4];
    #pragma unroll
    for (int mi = 0; mi < 4; mi++) aRow[mi] = wm * 64 + mi * 16 + (lane & 15);
    const int aG = (lane >> 4);
    int bRow[2];
    #pragma unroll
    for (int p = 0; p < 2; p++) bRow[p] = wn * 32 + p * 16 + (lane & 7) + ((lane & 16) >> 1);
    const int bG = (lane >> 3) & 1;

    #pragma unroll
    for (int s = 0; s < NSTG; s++) {
        load_stage(sb, s, s * BK, tid, Ah, Al, Bh, Bl);
        asm volatile("cp.async.commit_group;" ::: "memory");
    }

    for (int i = 0; i < NK; i++) {
        asm volatile("cp.async.wait_group 2;" ::: "memory");
        __syncthreads();

        const uint32_t aBase = sb + (i % NSTG) * STGB;
        const uint32_t bBase = aBase + TILEB;

        #pragma unroll
        for (int kstep = 0; kstep < 2; kstep++) {
            const int g0 = kstep * 2;

            uint32_t ah[4][4], bh2[2][4];
            #pragma unroll
            for (int mi = 0; mi < 4; mi++) {
                int r = aRow[mi];
                uint32_t ad = aBase + r * 128 + (((g0 + aG) ^ (r & 7)) << 4);
                LDSM4(ah[mi][0], ah[mi][1], ah[mi][2], ah[mi][3], ad);
            }
            #pragma unroll
            for (int p = 0; p < 2; p++) {
                int r = bRow[p];
                uint32_t bd = bBase + r * 128 + (((g0 + bG) ^ (r & 7)) << 4);
                LDSM4(bh2[p][0], bh2[p][1], bh2[p][2], bh2[p][3], bd);
            }
            #pragma unroll
            for (int mi = 0; mi < 4; mi++)
                #pragma unroll
                for (int ni = 0; ni < 4; ni++)
                    MMA16816(acc[mi][ni], ah[mi], bh2[ni >> 1][(ni & 1) * 2], bh2[ni >> 1][(ni & 1) * 2 + 1]);

            {
                uint32_t bl[2][4];
                #pragma unroll
                for (int p = 0; p < 2; p++) {
                    int r = bRow[p];
                    uint32_t bd = bBase + r * 128 + ((((4 + g0 + bG)) ^ (r & 7)) << 4);
                    LDSM4(bl[p][0], bl[p][1], bl[p][2], bl[p][3], bd);
                }
                #pragma unroll
                for (int mi = 0; mi < 4; mi++)
                    #pragma unroll
                    for (int ni = 0; ni < 4; ni++)
                        MMA16816(acc[mi][ni], ah[mi], bl[ni >> 1][(ni & 1) * 2], bl[ni >> 1][(ni & 1) * 2 + 1]);
            }
            {
                uint32_t al[4][4];
                #pragma unroll
                for (int mi = 0; mi < 4; mi++) {
                    int r = aRow[mi];
                    uint32_t ad = aBase + r * 128 + ((((4 + g0 + aG)) ^ (r & 7)) << 4);
                    LDSM4(al[mi][0], al[mi][1], al[mi][2], al[mi][3], ad);
                }
                #pragma unroll
                for (int mi = 0; mi < 4; mi++)
                    #pragma unroll
                    for (int ni = 0; ni < 4; ni++)
                        MMA16816(acc[mi][ni], al[mi], bh2[ni >> 1][(ni & 1) * 2], bh2[ni >> 1][(ni & 1) * 2 + 1]);
            }
        }

        __syncthreads();
        int nx = i + NSTG;
        if (nx < NK) load_stage(sb, i % NSTG, nx * BK, tid, Ah, Al, Bh, Bl);
        asm volatile("cp.async.commit_group;" ::: "memory");
    }

    // epilogue: z=0 -> Q bf16 hi/lo; z=1 -> K bf16 hi/lo; z=2 -> V fp32
    #pragma unroll
    for (int mi = 0; mi < 4; mi++) {
        #pragma unroll
        for (int ni = 0; ni < 4; ni++) {
            int m = m0 + wm * 64 + mi * 16 + (lane >> 2);
            int n = n0 + wn * 32 + ni * 8 + ((lane & 3) << 1);
            int h  = n >> 6;
            int dh = n & (DH_ - 1);
            #pragma unroll
            for (int half = 0; half < 2; half++) {
                int mm = m + half * 8;
                int b  = mm >> 11;
                int s  = mm & (S_ - 1);
                size_t eo = (((size_t)(b * H_ + h) * S_ + s) * DH_) + dh;
                float v0 = acc[mi][ni][half * 2];
                float v1 = acc[mi][ni][half * 2 + 1];
                if (z == 2) {
                    *(float2*)&g_v[eo] = make_float2(v0, v1);
                } else {
                    __nv_bfloat16 h0, l0, h1, l1;
                    bsplit(v0, h0, l0); bsplit(v1, h1, l1);
                    __nv_bfloat162* Ch = (__nv_bfloat162*)((z == 0) ? g_qh : g_kh);
                    __nv_bfloat162* Cl = (__nv_bfloat162*)((z == 0) ? g_ql : g_kl);
                    Ch[eo >> 1] = __nv_bfloat162(h0, h1);
                    Cl[eo >> 1] = __nv_bfloat162(l0, l1);
                }
            }
        }
    }
}

// ---------------------------------------------------------------------------
// V transpose + split: g_v [b,h][s][dh] fp32 -> g_vth/g_vtl [b,h][dh][s] bf16
// ---------------------------------------------------------------------------
__global__ __launch_bounds__(256) void vtrans()
{
    __shared__ float t[64][65];
    const int b = blockIdx.z, h = blockIdx.y, s0 = blockIdx.x * 64;
    const int tid = threadIdx.x;
    const size_t base = ((size_t)(b * H_ + h) * S_ + s0) * DH_;
    #pragma unroll
    for (int i = 0; i < 16; i++) {
        int idx = tid + i * 256;
        int sl = idx >> 6, dh = idx & 63;
        t[sl][dh] = g_v[base + (size_t)sl * DH_ + dh];
    }
    __syncthreads();
    const size_t ob = (size_t)(b * H_ + h) * DH_ * S_ + s0;
    #pragma unroll
    for (int i = 0; i < 16; i++) {
        int idx = tid + i * 256;
        int dh = idx >> 6, sl = idx & 63;
        __nv_bfloat16 hi, lo;
        bsplit(t[sl][dh], hi, lo);
        g_vth[ob + (size_t)dh * S_ + sl] = hi;
        g_vtl[ob + (size_t)dh * S_ + sl] = lo;
    }
}

// ---------------------------------------------------------------------------
// Tensor-core flash attention.
// grid (S/128, H, B), 256 thr (8 warps x 16 q-rows).  K tile = 64 keys.
// 3-term split bf16 for QK^T and PV; FFMA-only exp; online softmax in frags.
// smem: [0,32K) KV stage0, [32K,64K) KV stage1, [64K,96K) Qh/Ql staging.
//   KV stage: Kh[0,8K) Kl[8K,16K) Vh[16K,24K) Vl[24K,32K); rows 128B XOR-swz.
// ---------------------------------------------------------------------------
#define KT      64
#define NKT     (S_ / KT)       // 32
#define KV_STG  32768
#define OFF_Q   65536
#define SMEM_A  98304

__global__ __launch_bounds__(256) void attn_mma(float* __restrict__ out)
{
    extern __shared__ char sm[];
    const uint32_t sb = s2u(sm);
    const int tid = threadIdx.x, warp = tid >> 5, lane = tid & 31;
    const int b = blockIdx.z, h = blockIdx.y, q0 = blockIdx.x * 128;
    const size_t bh = (size_t)(b * H_ + h);

    const __nv_bfloat16* qhp = g_qh + bh * S_ * DH_ + (size_t)q0 * DH_;
    const __nv_bfloat16* qlp = g_ql + bh * S_ * DH_ + (size_t)q0 * DH_;
    const __nv_bfloat16* khp = g_kh + bh * S_ * DH_;
    const __nv_bfloat16* klp = g_kl + bh * S_ * DH_;
    const __nv_bfloat16* vhp = g_vth + bh * DH_ * S_;
    const __nv_bfloat16* vlp = g_vtl + bh * DH_ * S_;

    // ---- stage Q (group 0) ----
    #pragma unroll
    for (int j = 0; j < 8; j++) {
        int idx = tid + j * 256;            // 0..2047
        int sub = idx >> 10;                // 0 hi, 1 lo
        int r = (idx >> 3) & 127, c = idx & 7;
        uint32_t so = sb + OFF_Q + sub * 16384 + r * 128 + (((c) ^ (r & 7)) << 4);
        cp16(so, (sub ? qlp : qhp) + (size_t)r * DH_ + c * 8);
    }
    asm volatile("cp.async.commit_group;" ::: "memory");

    // ---- KV tile loader ----
    auto load_kv = [&](int st, int t) {
        const int s0 = t * KT;
        const uint32_t kvb = sb + st * KV_STG;
        #pragma unroll
        for (int j = 0; j < 8; j++) {
            int idx = tid + j * 256;        // 0..2047
            int sub = idx >> 9;             // 0 Kh, 1 Kl, 2 Vh, 3 Vl
            int r = (idx >> 3) & 63, c = idx & 7;
            uint32_t so = kvb + sub * 8192 + r * 128 + (((c) ^ (r & 7)) << 4);
            const __nv_bfloat16* src;
            if      (sub == 0) src = khp + (size_t)(s0 + r) * DH_ + c * 8;
            else if (sub == 1) src = klp + (size_t)(s0 + r) * DH_ + c * 8;
            else if (sub == 2) src = vhp + (size_t)r * S_ + s0 + c * 8;
            else               src = vlp + (size_t)r * S_ + s0 + c * 8;
            cp16(so, src);
        }
        asm volatile("cp.async.commit_group;" ::: "memory");
    };

    load_kv(0, 0);                          // group 1

    // wait for Q (oldest group), load Q frags
    asm volatile("cp.async.wait_group 1;" ::: "memory");
    __syncthreads();

    uint32_t Qh[4][4], Ql[4][4];
    {
        const int ar = warp * 16 + (lane & 15);
        const int ag = lane >> 4;
        #pragma unroll
        for (int kc = 0; kc < 4; kc++) {
            uint32_t ad = sb + OFF_Q + ar * 128 + (((kc * 2 + ag) ^ (ar & 7)) << 4);
            LDSM4(Qh[kc][0], Qh[kc][1], Qh[kc][2], Qh[kc][3], ad);
            ad += 16384;
            LDSM4(Ql[kc][0], Ql[kc][1], Ql[kc][2], Ql[kc][3], ad);
        }
    }

    float o[8][4];
    #pragma unroll
    for (int j = 0; j < 8; j++)
        #pragma unroll
        for (int r = 0; r < 4; r++) o[j][r] = 0.f;
    float m0 = -1e30f, m1 = -1e30f, l0 = 0.f, l1 = 0.f;

    const int brb = (lane & 7) + ((lane & 16) >> 1);
    const int bg  = (lane >> 3) & 1;

    for (int t = 0; t < NKT; t++) {
        if (t + 1 < NKT) load_kv((t + 1) & 1, t + 1);
        asm volatile("cp.async.wait_group 1;" ::: "memory");
        __syncthreads();

        const uint32_t kvb = sb + (t & 1) * KV_STG;

        // ---- S = Q K^T (3 terms) ----
        float s[8][4];
        #pragma unroll
        for (int j = 0; j < 8; j++)
            #pragma unroll
            for (int r = 0; r < 4; r++) s[j][r] = 0.f;

        #pragma unroll
        for (int kc = 0; kc < 4; kc++) {
            const int g = kc * 2 + bg;
            uint32_t kf[4][4], lf[4][4];
            #pragma unroll
            for (int nt = 0; nt < 4; nt++) {
                int r = nt * 16 + brb;
                uint32_t off = r * 128 + ((g ^ (r & 7)) << 4);
                LDSM4(kf[nt][0], kf[nt][1], kf[nt][2], kf[nt][3], kvb + off);
                LDSM4(lf[nt][0], lf[nt][1], lf[nt][2], lf[nt][3], kvb + 8192 + off);
            }
            #pragma unroll
            for (int nt = 0; nt < 4; nt++)
                #pragma unroll
                for (int h2 = 0; h2 < 2; h2++) {
                    int ni = nt * 2 + h2;
                    MMA16816(s[ni], Qh[kc], kf[nt][h2 * 2], kf[nt][h2 * 2 + 1]);
                    MMA16816(s[ni], Ql[kc], kf[nt][h2 * 2], kf[nt][h2 * 2 + 1]);
                    MMA16816(s[ni], Qh[kc], lf[nt][h2 * 2], lf[nt][h2 * 2 + 1]);
                }
        }

        // ---- online softmax (rows r0 = lane>>2, r1 = r0+8; quad reduction) ----
        float mt0 = -1e30f, mt1 = -1e30f;
        #pragma unroll
        for (int j = 0; j < 8; j++) {
            mt0 = fmaxf(mt0, fmaxf(s[j][0], s[j][1]));
            mt1 = fmaxf(mt1, fmaxf(s[j][2], s[j][3]));
        }
        mt0 *= 0.0625f; mt1 *= 0.0625f;
        mt0 = fmaxf(mt0, __shfl_xor_sync(0xFFFFFFFFu, mt0, 1));
        mt0 = fmaxf(mt0, __shfl_xor_sync(0xFFFFFFFFu, mt0, 2));
        mt1 = fmaxf(mt1, __shfl_xor_sync(0xFFFFFFFFu, mt1, 1));
        mt1 = fmaxf(mt1, __shfl_xor_sync(0xFFFFFFFFu, mt1, 2));
        const float mn0 = fmaxf(m0, mt0), mn1 = fmaxf(m1, mt1);
        const float sc0 = fexp(m0 - mn0), sc1 = fexp(m1 - mn1);
        m0 = mn0; m1 = mn1;
        l0 *= sc0; l1 *= sc1;
        #pragma unroll
        for (int j = 0; j < 8; j++) {
            o[j][0] *= sc0; o[j][1] *= sc0;
            o[j][2] *= sc1; o[j][3] *= sc1;
        }
        #pragma unroll
        for (int j = 0; j < 8; j++) {
            float p0 = fexp(fmaf(s[j][0], 0.0625f, -mn0));
            float p1 = fexp(fmaf(s[j][1], 0.0625f, -mn0));
            float p2 = fexp(fmaf(s[j][2], 0.0625f, -mn1));
            float p3 = fexp(fmaf(s[j][3], 0.0625f, -mn1));
            l0 += p0 + p1; l1 += p2 + p3;
            s[j][0] = p0; s[j][1] = p1; s[j][2] = p2; s[j][3] = p3;
        }

        // ---- O += P V (3 terms) ----
        #pragma unroll
        for (int kc = 0; kc < 4; kc++) {
            const int g = kc * 2 + bg;
            uint32_t vh4[4][4], vl4[4][4];
            #pragma unroll
            for (int nt = 0; nt < 4; nt++) {
                int r = nt * 16 + brb;
                uint32_t off = r * 128 + ((g ^ (r & 7)) << 4);
                LDSM4(vh4[nt][0], vh4[nt][1], vh4[nt][2], vh4[nt][3], kvb + 16384 + off);
                LDSM4(vl4[nt][0], vl4[nt][1], vl4[nt][2], vl4[nt][3], kvb + 24576 + off);
            }
            uint32_t Ahf[4], Alf[4];
            split2(s[2 * kc][0],     s[2 * kc][1],     Ahf[0], Alf[0]);
            split2(s[2 * kc][2],     s[2 * kc][3],     Ahf[1], Alf[1]);
            split2(s[2 * kc + 1][0], s[2 * kc + 1][1], Ahf[2], Alf[2]);
            split2(s[2 * kc + 1][2], s[2 * kc + 1][3], Ahf[3], Alf[3]);
            #pragma unroll
            for (int nt = 0; nt < 4; nt++)
                #pragma unroll
                for (int h2 = 0; h2 < 2; h2++) {
                    int ni = nt * 2 + h2;
                    MMA16816(o[ni], Ahf, vh4[nt][h2 * 2], vh4[nt][h2 * 2 + 1]);
                    MMA16816(o[ni], Ahf, vl4[nt][h2 * 2], vl4[nt][h2 * 2 + 1]);
                    MMA16816(o[ni], Alf, vh4[nt][h2 * 2], vh4[nt][h2 * 2 + 1]);
                }
        }
        __syncthreads();
    }

    // ---- epilogue ----
    l0 += __shfl_xor_sync(0xFFFFFFFFu, l0, 1);
    l0 += __shfl_xor_sync(0xFFFFFFFFu, l0, 2);
    l1 += __shfl_xor_sync(0xFFFFFFFFu, l1, 1);
    l1 += __shfl_xor_sync(0xFFFFFFFFu, l1, 2);
    const float i0 = 1.0f / l0, i1 = 1.0f / l1;

    const int q = q0 + warp * 16 + (lane >> 2);
    float* op = out + ((size_t)b * S_ + q) * D_ + h * DH_;
    #pragma unroll
    for (int j = 0; j < 8; j++) {
        int dh = j * 8 + ((lane & 3) << 1);
        *(float2*)(op + dh)            = make_float2(o[j][0] * i0, o[j][1] * i0);
        *(float2*)(op + 8 * D_ + dh)   = make_float2(o[j][2] * i1, o[j][3] * i1);
    }
}

// ---------------------------------------------------------------------------
// Launch
// ---------------------------------------------------------------------------
extern "C" void kernel_launch(void* const* d_in, const int* in_sizes, int n_in,
                              void* d_out, int out_size)
{
    const float* x  = (const float*)d_in[0];
    const float* wq = (const float*)d_in[1];
    const float* wk = (const float*)d_in[2];
    const float* wv = (const float*)d_in[3];
    float* out = (float*)d_out;

    static bool attr_set = false;
    if (!attr_set) {
        cudaFuncSetAttribute(qkv_gemm_mma,
                             cudaFuncAttributeMaxDynamicSharedMemorySize, SMEM_G);
        cudaFuncSetAttribute(attn_mma,
                             cudaFuncAttributeMaxDynamicSharedMemorySize, SMEM_A);
        attr_set = true;
    }

    xsplit<<<(M_ * D_ / 4) / 256, 256>>>(x);
    wsplit<<<dim3(32, 32, 3), dim3(32, 8)>>>(wq, wk, wv);
    qkv_gemm_mma<<<dim3(D_ / 128, M_ / 128, 3), 256, SMEM_G>>>();
    vtrans<<<dim3(S_ / 64, H_, B_), 256>>>();
    attn_mma<<<dim3(S_ / 128, H_, B_), 256, SMEM_A>>>(out);
}

// round 5
// speedup vs baseline: 3.8551x; 1.1607x over previous
#include <cuda_runtime.h>
#include <cuda_bf16.h>
#include <cstdint>

#define B_  4
#define S_  2048
#define D_  1024
#define H_  16
#define DH_ 64
#define M_  (B_ * S_)   // 8192

// ---------------- device scratch: pre-swizzled tile images ------------------
// A image: [m-panel 64][k-chunk 32][16KB]  (128 rows x 128B; chunks 0-3 hi, 4-7 lo)
__device__ unsigned char g_aimg[64 * 32 * 16384];
// B image: [z 3][n-panel 8][k-chunk 32][16KB]
__device__ unsigned char g_bimg[3 * 8 * 32 * 16384];
// Q image: [bh 64][q-panel 16][32KB]  (hi 16KB then lo 16KB; 128 rows x 128B)
__device__ unsigned char g_qimg[64 * 16 * 32768];
// KV image: [bh 64][s-tile 32][32KB]  (Kh 8K | Kl 8K | Vh 8K | Vl 8K; 64 rows x 128B)
__device__ unsigned char g_kvimg[64 * 32 * 32768];
__device__ float g_v[B_ * H_ * S_ * DH_];

#define SWZ(c, r) ((((c) ^ ((r) & 7)) << 4))

// ---------------- helpers ----------------------------------------------------
static __device__ __forceinline__ uint32_t s2u(const void* p) {
    uint32_t a;
    asm("{ .reg .u64 t; cvta.to.shared.u64 t, %1; cvt.u32.u64 %0, t; }"
        : "=r"(a) : "l"(p));
    return a;
}

static __device__ __forceinline__ void mbar_init(uint32_t a, uint32_t cnt) {
    asm volatile("mbarrier.init.shared.b64 [%0], %1;" :: "r"(a), "r"(cnt) : "memory");
}
static __device__ __forceinline__ void mbar_expect_tx(uint32_t a, uint32_t bytes) {
    asm volatile("mbarrier.arrive.expect_tx.shared.b64 _, [%0], %1;"
                 :: "r"(a), "r"(bytes) : "memory");
}
static __device__ __forceinline__ void mbar_wait(uint32_t a, uint32_t parity) {
    asm volatile(
        "{\n\t.reg .pred P;\n\t"
        "W_%=:\n\t"
        "mbarrier.try_wait.parity.shared::cta.b64 P, [%0], %1;\n\t"
        "@!P bra W_%=;\n\t}"
        :: "r"(a), "r"(parity) : "memory");
}
static __device__ __forceinline__ void bulk_g2s(uint32_t dst, const void* src,
                                                uint32_t bytes, uint32_t mbar) {
    asm volatile(
        "cp.async.bulk.shared::cluster.global.mbarrier::complete_tx::bytes "
        "[%0], [%1], %2, [%3];"
        :: "r"(dst), "l"(__cvta_generic_to_global(src)), "r"(bytes), "r"(mbar)
        : "memory");
}

#define LDSM4(r0, r1, r2, r3, a)                                            \
    asm volatile("ldmatrix.sync.aligned.m8n8.x4.shared.b16 "                \
                 "{%0,%1,%2,%3}, [%4];"                                     \
                 : "=r"(r0), "=r"(r1), "=r"(r2), "=r"(r3) : "r"(a))

#define MMA16816(d, a, b0v, b1v)                                            \
    asm volatile("mma.sync.aligned.m16n8k16.row.col.f32.bf16.bf16.f32 "     \
                 "{%0,%1,%2,%3}, {%4,%5,%6,%7}, {%8,%9}, {%0,%1,%2,%3};"    \
                 : "+f"((d)[0]), "+f"((d)[1]), "+f"((d)[2]), "+f"((d)[3])   \
                 : "r"((a)[0]), "r"((a)[1]), "r"((a)[2]), "r"((a)[3]),      \
                   "r"(b0v), "r"(b1v))

static __device__ __forceinline__ void bsplit(float v, __nv_bfloat16& h, __nv_bfloat16& l) {
    h = __float2bfloat16(v);
    l = __float2bfloat16(v - __bfloat162float(h));
}

static __device__ __forceinline__ uint32_t pk(__nv_bfloat16 a, __nv_bfloat16 b) {
    return (uint32_t)__bfloat16_as_ushort(a) | ((uint32_t)__bfloat16_as_ushort(b) << 16);
}

static __device__ __forceinline__ void split2(float a, float b, uint32_t& hi, uint32_t& lo) {
    __nv_bfloat16 ha = __float2bfloat16(a), hb = __float2bfloat16(b);
    __nv_bfloat16 la = __float2bfloat16(a - __bfloat162float(ha));
    __nv_bfloat16 lb = __float2bfloat16(b - __bfloat162float(hb));
    hi = pk(ha, hb);
    lo = pk(la, lb);
}

// FFMA-only exp (no MUFU): exp(x) for x <= ~0, clamped at -87.
static __device__ __forceinline__ float fexp(float x) {
    x = fmaxf(x, -87.0f);
    float t = x * 1.4426950408889634f;
    float n = t + 12582912.0f;
    int   e = __float_as_int(n) - 0x4B400000;
    float fn = n - 12582912.0f;
    float f  = t - fn;
    float p = 0.0013333558f;
    p = fmaf(p, f, 0.0096181291f);
    p = fmaf(p, f, 0.0555041087f);
    p = fmaf(p, f, 0.2402265069f);
    p = fmaf(p, f, 0.6931471806f);
    p = fmaf(p, f, 1.0f);
    return p * __int_as_float((e + 127) << 23);
}

// ---------------------------------------------------------------------------
// Preprocessing: split X into bf16 hi/lo, writing the A tile image.
// ---------------------------------------------------------------------------
__global__ void xsplit(const float* __restrict__ x)
{
    int i = blockIdx.x * 256 + threadIdx.x;      // 8-float chunk index (1M total)
    int l = i * 8;
    int m = l >> 10, k = l & (D_ - 1);
    float4 v0 = ((const float4*)x)[2 * i];
    float4 v1 = ((const float4*)x)[2 * i + 1];
    float vv[8] = {v0.x, v0.y, v0.z, v0.w, v1.x, v1.y, v1.z, v1.w};
    __nv_bfloat16 hi[8], lo[8];
    #pragma unroll
    for (int j = 0; j < 8; j++) bsplit(vv[j], hi[j], lo[j]);
    uint4 h4 = make_uint4(pk(hi[0], hi[1]), pk(hi[2], hi[3]), pk(hi[4], hi[5]), pk(hi[6], hi[7]));
    uint4 l4 = make_uint4(pk(lo[0], lo[1]), pk(lo[2], lo[3]), pk(lo[4], lo[5]), pk(lo[6], lo[7]));
    size_t base = ((size_t)(m >> 7) * 32 + (k >> 5)) * 16384;
    int r = m & 127, c = (k >> 3) & 3;
    *(uint4*)&g_aimg[base + r * 128 + SWZ(c, r)]     = h4;
    *(uint4*)&g_aimg[base + r * 128 + SWZ(c + 4, r)] = l4;
}

// ---------------------------------------------------------------------------
// Preprocessing: transpose + split W, writing the B tile image.
// ---------------------------------------------------------------------------
__global__ void wsplit(const float* __restrict__ Wq,
                       const float* __restrict__ Wk,
                       const float* __restrict__ Wv)
{
    __shared__ float t[32][33];
    const int z = blockIdx.z;
    const float* W = (z == 0) ? Wq : (z == 1) ? Wk : Wv;
    const int n  = blockIdx.x * 32 + threadIdx.x;
    const int k0 = blockIdx.y * 32;
    #pragma unroll
    for (int dy = 0; dy < 32; dy += 8) {
        int k = k0 + threadIdx.y + dy;
        t[threadIdx.y + dy][threadIdx.x] = W[(size_t)k * D_ + n];
    }
    __syncthreads();
    const int kk = k0 + threadIdx.x;
    #pragma unroll
    for (int dy = 0; dy < 32; dy += 8) {
        int nn = blockIdx.x * 32 + threadIdx.y + dy;
        float v = t[threadIdx.x][threadIdx.y + dy];
        __nv_bfloat16 hi, lo;
        bsplit(v, hi, lo);
        size_t base = ((size_t)(z * 8 + (nn >> 7)) * 32 + (kk >> 5)) * 16384;
        int r = nn & 127, c = (kk >> 3) & 3, byb = (kk & 7) * 2;
        *(unsigned short*)&g_bimg[base + r * 128 + SWZ(c, r) + byb]     = __bfloat16_as_ushort(hi);
        *(unsigned short*)&g_bimg[base + r * 128 + SWZ(c + 4, r) + byb] = __bfloat16_as_ushort(lo);
    }
}

// ---------------------------------------------------------------------------
// QKV GEMM via mma.sync bf16, 3-term split.  Stages loaded by cp.async.bulk.
// ---------------------------------------------------------------------------
#define NK     32
#define SMEM_G (1024 + 3 * 32768)

__global__ __launch_bounds__(256) void qkv_gemm_mma()
{
    extern __shared__ char smem[];
    const uint32_t sb = s2u(smem);
    const int tid  = threadIdx.x;
    const int warp = tid >> 5;
    const int lane = tid & 31;
    const int wm   = warp & 1;
    const int wn   = warp >> 1;

    const int n0 = blockIdx.x * 128;
    const int m0 = blockIdx.y * 128;
    const int z  = blockIdx.z;

    if (tid == 0) {
        mbar_init(sb + 0, 1);
        mbar_init(sb + 8, 1);
        mbar_init(sb + 16, 1);
    }
    __syncthreads();

    const unsigned char* Asrc = g_aimg + (size_t)blockIdx.y * 32 * 16384;
    const unsigned char* Bsrc = g_bimg + (size_t)(z * 8 + blockIdx.x) * 32 * 16384;

    if (tid == 0) {
        #pragma unroll
        for (int s = 0; s < 3; s++) {
            mbar_expect_tx(sb + 8 * s, 32768);
            bulk_g2s(sb + 1024 + s * 32768,         Asrc + s * 16384, 16384, sb + 8 * s);
            bulk_g2s(sb + 1024 + s * 32768 + 16384, Bsrc + s * 16384, 16384, sb + 8 * s);
        }
    }

    float acc[4][4][4];
    #pragma unroll
    for (int mi = 0; mi < 4; mi++)
        #pragma unroll
        for (int ni = 0; ni < 4; ni++)
            #pragma unroll
            for (int r = 0; r < 4; r++) acc[mi][ni][r] = 0.f;

    int aRow[4];
    #pragma unroll
    for (int mi = 0; mi < 4; mi++) aRow[mi] = wm * 64 + mi * 16 + (lane & 15);
    const int aG = (lane >> 4);
    int bRow[2];
    #pragma unroll
    for (int p = 0; p < 2; p++) bRow[p] = wn * 32 + p * 16 + (lane & 7) + ((lane & 16) >> 1);
    const int bG = (lane >> 3) & 1;

    for (int i = 0; i < NK; i++) {
        const int s = i % 3;
        const uint32_t parity = (uint32_t)((i / 3) & 1);
        mbar_wait(sb + 8 * s, parity);

        const uint32_t aBase = sb + 1024 + s * 32768;
        const uint32_t bBase = aBase + 16384;

        #pragma unroll
        for (int kstep = 0; kstep < 2; kstep++) {
            const int g0 = kstep * 2;

            uint32_t ah[4][4], bh2[2][4];
            #pragma unroll
            for (int mi = 0; mi < 4; mi++) {
                int r = aRow[mi];
                uint32_t ad = aBase + r * 128 + (((g0 + aG) ^ (r & 7)) << 4);
                LDSM4(ah[mi][0], ah[mi][1], ah[mi][2], ah[mi][3], ad);
            }
            #pragma unroll
            for (int p = 0; p < 2; p++) {
                int r = bRow[p];
                uint32_t bd = bBase + r * 128 + (((g0 + bG) ^ (r & 7)) << 4);
                LDSM4(bh2[p][0], bh2[p][1], bh2[p][2], bh2[p][3], bd);
            }
            #pragma unroll
            for (int mi = 0; mi < 4; mi++)
                #pragma unroll
                for (int ni = 0; ni < 4; ni++)
                    MMA16816(acc[mi][ni], ah[mi], bh2[ni >> 1][(ni & 1) * 2], bh2[ni >> 1][(ni & 1) * 2 + 1]);

            {
                uint32_t bl[2][4];
                #pragma unroll
                for (int p = 0; p < 2; p++) {
                    int r = bRow[p];
                    uint32_t bd = bBase + r * 128 + ((((4 + g0 + bG)) ^ (r & 7)) << 4);
                    LDSM4(bl[p][0], bl[p][1], bl[p][2], bl[p][3], bd);
                }
                #pragma unroll
                for (int mi = 0; mi < 4; mi++)
                    #pragma unroll
                    for (int ni = 0; ni < 4; ni++)
                        MMA16816(acc[mi][ni], ah[mi], bl[ni >> 1][(ni & 1) * 2], bl[ni >> 1][(ni & 1) * 2 + 1]);
            }
            {
                uint32_t al[4][4];
                #pragma unroll
                for (int mi = 0; mi < 4; mi++) {
                    int r = aRow[mi];
                    uint32_t ad = aBase + r * 128 + ((((4 + g0 + aG)) ^ (r & 7)) << 4);
                    LDSM4(al[mi][0], al[mi][1], al[mi][2], al[mi][3], ad);
                }
                #pragma unroll
                for (int mi = 0; mi < 4; mi++)
                    #pragma unroll
                    for (int ni = 0; ni < 4; ni++)
                        MMA16816(acc[mi][ni], al[mi], bh2[ni >> 1][(ni & 1) * 2], bh2[ni >> 1][(ni & 1) * 2 + 1]);
            }
        }

        __syncthreads();
        const int nx = i + 3;
        if (nx < NK && tid == 0) {
            mbar_expect_tx(sb + 8 * s, 32768);
            bulk_g2s(aBase, Asrc + nx * 16384, 16384, sb + 8 * s);
            bulk_g2s(bBase, Bsrc + nx * 16384, 16384, sb + 8 * s);
        }
    }

    // epilogue: z=0 -> Q image; z=1 -> K part of KV image; z=2 -> V fp32
    #pragma unroll
    for (int mi = 0; mi < 4; mi++) {
        #pragma unroll
        for (int ni = 0; ni < 4; ni++) {
            int m = m0 + wm * 64 + mi * 16 + (lane >> 2);
            int n = n0 + wn * 32 + ni * 8 + ((lane & 3) << 1);
            int h  = n >> 6;
            int dh = n & (DH_ - 1);
            #pragma unroll
            for (int half = 0; half < 2; half++) {
                int mm = m + half * 8;
                int b  = mm >> 11;
                int sq = mm & (S_ - 1);
                float v0 = acc[mi][ni][half * 2];
                float v1 = acc[mi][ni][half * 2 + 1];
                if (z == 2) {
                    *(float2*)&g_v[(((size_t)(b * H_ + h) * S_ + sq) * DH_) + dh] =
                        make_float2(v0, v1);
                } else {
                    __nv_bfloat16 h0, l0, h1, l1;
                    bsplit(v0, h0, l0); bsplit(v1, h1, l1);
                    size_t bh = (size_t)b * H_ + h;
                    if (z == 0) {
                        size_t ob = (bh * 16 + (sq >> 7)) * 32768
                                  + (size_t)(sq & 127) * 128
                                  + SWZ(dh >> 3, sq & 127) + (dh & 7) * 2;
                        *(__nv_bfloat162*)&g_qimg[ob]         = __nv_bfloat162(h0, h1);
                        *(__nv_bfloat162*)&g_qimg[ob + 16384] = __nv_bfloat162(l0, l1);
                    } else {
                        size_t ob = (bh * 32 + (sq >> 6)) * 32768
                                  + (size_t)(sq & 63) * 128
                                  + SWZ(dh >> 3, sq & 63) + (dh & 7) * 2;
                        *(__nv_bfloat162*)&g_kvimg[ob]        = __nv_bfloat162(h0, h1);
                        *(__nv_bfloat162*)&g_kvimg[ob + 8192] = __nv_bfloat162(l0, l1);
                    }
                }
            }
        }
    }
}

// ---------------------------------------------------------------------------
// V transpose + split into KV image (Vh @ +16384, Vl @ +24576).
// ---------------------------------------------------------------------------
__global__ __launch_bounds__(256) void vtrans()
{
    __shared__ float t[64][65];
    const int b = blockIdx.z, h = blockIdx.y;
    const int s0 = blockIdx.x * 64;
    const int tid = threadIdx.x;
    const size_t bh = (size_t)b * H_ + h;
    const size_t base_in = (bh * S_ + s0) * DH_;
    #pragma unroll
    for (int i = 0; i < 16; i++) {
        int idx = tid + i * 256;
        int sl = idx >> 6, dh = idx & 63;
        t[sl][dh] = g_v[base_in + (size_t)sl * DH_ + dh];
    }
    __syncthreads();
    const size_t base = (bh * 32 + blockIdx.x) * 32768 + 16384;
    #pragma unroll
    for (int i = 0; i < 8; i++) {
        int idx = (tid + i * 256) * 2;
        int dh = idx >> 6, sl = idx & 63;       // sl even
        __nv_bfloat16 ha, la, hb, lb;
        bsplit(t[sl][dh], ha, la);
        bsplit(t[sl + 1][dh], hb, lb);
        uint32_t off = dh * 128 + SWZ((sl >> 3) & 7, dh) + (sl & 7) * 2;
        *(__nv_bfloat162*)&g_kvimg[base + off]        = __nv_bfloat162(ha, hb);
        *(__nv_bfloat162*)&g_kvimg[base + 8192 + off] = __nv_bfloat162(la, lb);
    }
}

// ---------------------------------------------------------------------------
// Tensor-core flash attention; stages via cp.async.bulk.
// smem: mbars @ [0,1024); KV stage0 @1024, stage1 @1024+32K, Q @1024+64K.
// ---------------------------------------------------------------------------
#define NKT    32
#define SMEM_A (1024 + 3 * 32768)
#define OFF_Q  (1024 + 65536)

__global__ __launch_bounds__(256) void attn_mma(float* __restrict__ out)
{
    extern __shared__ char sm[];
    const uint32_t sb = s2u(sm);
    const int tid = threadIdx.x, warp = tid >> 5, lane = tid & 31;
    const int b = blockIdx.z, h = blockIdx.y, q0 = blockIdx.x * 128;
    const size_t bh = (size_t)(b * H_ + h);

    const unsigned char* Qsrc  = g_qimg + (bh * 16 + blockIdx.x) * 32768;
    const unsigned char* KVsrc = g_kvimg + bh * 32 * 32768;

    if (tid == 0) {
        mbar_init(sb + 0, 1);      // Q
        mbar_init(sb + 8, 1);      // KV stage 0
        mbar_init(sb + 16, 1);     // KV stage 1
    }
    __syncthreads();

    if (tid == 0) {
        mbar_expect_tx(sb, 32768);
        bulk_g2s(sb + OFF_Q, Qsrc, 32768, sb);
        mbar_expect_tx(sb + 8, 32768);
        bulk_g2s(sb + 1024, KVsrc, 32768, sb + 8);
    }

    mbar_wait(sb, 0);

    uint32_t Qh[4][4], Ql[4][4];
    {
        const int ar = warp * 16 + (lane & 15);
        const int ag = lane >> 4;
        #pragma unroll
        for (int kc = 0; kc < 4; kc++) {
            uint32_t ad = sb + OFF_Q + ar * 128 + (((kc * 2 + ag) ^ (ar & 7)) << 4);
            LDSM4(Qh[kc][0], Qh[kc][1], Qh[kc][2], Qh[kc][3], ad);
            ad += 16384;
            LDSM4(Ql[kc][0], Ql[kc][1], Ql[kc][2], Ql[kc][3], ad);
        }
    }

    float o[8][4];
    #pragma unroll
    for (int j = 0; j < 8; j++)
        #pragma unroll
        for (int r = 0; r < 4; r++) o[j][r] = 0.f;
    float m0 = -1e30f, m1 = -1e30f, l0 = 0.f, l1 = 0.f;

    const int brb = (lane & 7) + ((lane & 16) >> 1);
    const int bg  = (lane >> 3) & 1;

    for (int t = 0; t < NKT; t++) {
        if (t + 1 < NKT && tid == 0) {
            const int st = (t + 1) & 1;
            mbar_expect_tx(sb + 8 + 8 * st, 32768);
            bulk_g2s(sb + 1024 + st * 32768, KVsrc + (size_t)(t + 1) * 32768,
                     32768, sb + 8 + 8 * st);
        }
        mbar_wait(sb + 8 + 8 * (t & 1), (uint32_t)((t >> 1) & 1));

        const uint32_t kvb = sb + 1024 + (t & 1) * 32768;

        // ---- S = Q K^T (3 terms) ----
        float s[8][4];
        #pragma unroll
        for (int j = 0; j < 8; j++)
            #pragma unroll
            for (int r = 0; r < 4; r++) s[j][r] = 0.f;

        #pragma unroll
        for (int kc = 0; kc < 4; kc++) {
            const int g = kc * 2 + bg;
            uint32_t kf[4][4], lf[4][4];
            #pragma unroll
            for (int nt = 0; nt < 4; nt++) {
                int r = nt * 16 + brb;
                uint32_t off = r * 128 + ((g ^ (r & 7)) << 4);
                LDSM4(kf[nt][0], kf[nt][1], kf[nt][2], kf[nt][3], kvb + off);
                LDSM4(lf[nt][0], lf[nt][1], lf[nt][2], lf[nt][3], kvb + 8192 + off);
            }
            #pragma unroll
            for (int nt = 0; nt < 4; nt++)
                #pragma unroll
                for (int h2 = 0; h2 < 2; h2++) {
                    int ni = nt * 2 + h2;
                    MMA16816(s[ni], Qh[kc], kf[nt][h2 * 2], kf[nt][h2 * 2 + 1]);
                    MMA16816(s[ni], Ql[kc], kf[nt][h2 * 2], kf[nt][h2 * 2 + 1]);
                    MMA16816(s[ni], Qh[kc], lf[nt][h2 * 2], lf[nt][h2 * 2 + 1]);
                }
        }

        // ---- online softmax ----
        float mt0 = -1e30f, mt1 = -1e30f;
        #pragma unroll
        for (int j = 0; j < 8; j++) {
            mt0 = fmaxf(mt0, fmaxf(s[j][0], s[j][1]));
            mt1 = fmaxf(mt1, fmaxf(s[j][2], s[j][3]));
        }
        mt0 *= 0.0625f; mt1 *= 0.0625f;
        mt0 = fmaxf(mt0, __shfl_xor_sync(0xFFFFFFFFu, mt0, 1));
        mt0 = fmaxf(mt0, __shfl_xor_sync(0xFFFFFFFFu, mt0, 2));
        mt1 = fmaxf(mt1, __shfl_xor_sync(0xFFFFFFFFu, mt1, 1));
        mt1 = fmaxf(mt1, __shfl_xor_sync(0xFFFFFFFFu, mt1, 2));
        const float mn0 = fmaxf(m0, mt0), mn1 = fmaxf(m1, mt1);
        const float sc0 = fexp(m0 - mn0), sc1 = fexp(m1 - mn1);
        m0 = mn0; m1 = mn1;
        l0 *= sc0; l1 *= sc1;
        #pragma unroll
        for (int j = 0; j < 8; j++) {
            o[j][0] *= sc0; o[j][1] *= sc0;
            o[j][2] *= sc1; o[j][3] *= sc1;
        }
        #pragma unroll
        for (int j = 0; j < 8; j++) {
            float p0 = fexp(fmaf(s[j][0], 0.0625f, -mn0));
            float p1 = fexp(fmaf(s[j][1], 0.0625f, -mn0));
            float p2 = fexp(fmaf(s[j][2], 0.0625f, -mn1));
            float p3 = fexp(fmaf(s[j][3], 0.0625f, -mn1));
            l0 += p0 + p1; l1 += p2 + p3;
            s[j][0] = p0; s[j][1] = p1; s[j][2] = p2; s[j][3] = p3;
        }

        // ---- O += P V (3 terms) ----
        #pragma unroll
        for (int kc = 0; kc < 4; kc++) {
            const int g = kc * 2 + bg;
            uint32_t vh4[4][4], vl4[4][4];
            #pragma unroll
            for (int nt = 0; nt < 4; nt++) {
                int r = nt * 16 + brb;
                uint32_t off = r * 128 + ((g ^ (r & 7)) << 4);
                LDSM4(vh4[nt][0], vh4[nt][1], vh4[nt][2], vh4[nt][3], kvb + 16384 + off);
                LDSM4(vl4[nt][0], vl4[nt][1], vl4[nt][2], vl4[nt][3], kvb + 24576 + off);
            }
            uint32_t Ahf[4], Alf[4];
            split2(s[2 * kc][0],     s[2 * kc][1],     Ahf[0], Alf[0]);
            split2(s[2 * kc][2],     s[2 * kc][3],     Ahf[1], Alf[1]);
            split2(s[2 * kc + 1][0], s[2 * kc + 1][1], Ahf[2], Alf[2]);
            split2(s[2 * kc + 1][2], s[2 * kc + 1][3], Ahf[3], Alf[3]);
            #pragma unroll
            for (int nt = 0; nt < 4; nt++)
                #pragma unroll
                for (int h2 = 0; h2 < 2; h2++) {
                    int ni = nt * 2 + h2;
                    MMA16816(o[ni], Ahf, vh4[nt][h2 * 2], vh4[nt][h2 * 2 + 1]);
                    MMA16816(o[ni], Ahf, vl4[nt][h2 * 2], vl4[nt][h2 * 2 + 1]);
                    MMA16816(o[ni], Alf, vh4[nt][h2 * 2], vh4[nt][h2 * 2 + 1]);
                }
        }
        __syncthreads();
    }

    // ---- epilogue ----
    l0 += __shfl_xor_sync(0xFFFFFFFFu, l0, 1);
    l0 += __shfl_xor_sync(0xFFFFFFFFu, l0, 2);
    l1 += __shfl_xor_sync(0xFFFFFFFFu, l1, 1);
    l1 += __shfl_xor_sync(0xFFFFFFFFu, l1, 2);
    const float i0 = 1.0f / l0, i1 = 1.0f / l1;

    const int q = q0 + warp * 16 + (lane >> 2);
    float* op = out + ((size_t)b * S_ + q) * D_ + h * DH_;
    #pragma unroll
    for (int j = 0; j < 8; j++) {
        int dh = j * 8 + ((lane & 3) << 1);
        *(float2*)(op + dh)          = make_float2(o[j][0] * i0, o[j][1] * i0);
        *(float2*)(op + 8 * D_ + dh) = make_float2(o[j][2] * i1, o[j][3] * i1);
    }
}

// ---------------------------------------------------------------------------
// Launch
// ---------------------------------------------------------------------------
extern "C" void kernel_launch(void* const* d_in, const int* in_sizes, int n_in,
                              void* d_out, int out_size)
{
    const float* x  = (const float*)d_in[0];
    const float* wq = (const float*)d_in[1];
    const float* wk = (const float*)d_in[2];
    const float* wv = (const float*)d_in[3];
    float* out = (float*)d_out;

    static bool attr_set = false;
    if (!attr_set) {
        cudaFuncSetAttribute(qkv_gemm_mma,
                             cudaFuncAttributeMaxDynamicSharedMemorySize, SMEM_G);
        cudaFuncSetAttribute(attn_mma,
                             cudaFuncAttributeMaxDynamicSharedMemorySize, SMEM_A);
        attr_set = true;
    }

    xsplit<<<(M_ * D_ / 8) / 256, 256>>>(x);
    wsplit<<<dim3(32, 32, 3), dim3(32, 8)>>>(wq, wk, wv);
    qkv_gemm_mma<<<dim3(D_ / 128, M_ / 128, 3), 256, SMEM_G>>>();
    vtrans<<<dim3(S_ / 64, H_, B_), 256>>>();
    attn_mma<<<dim3(S_ / 128, H_, B_), 256, SMEM_A>>>(out);
}

// round 6
// speedup vs baseline: 4.4856x; 1.1636x over previous
#include <cuda_runtime.h>
#include <cuda_fp16.h>
#include <cstdint>

#define B_  4
#define S_  2048
#define D_  1024
#define H_  16
#define DH_ 64
#define M_  (B_ * S_)   // 8192

// ---------------- device scratch: pre-swizzled tile images ------------------
// A image: [m-panel 64][k-chunk 32][16KB]  (128 rows x 128B; chunks 0-3 hi, 4-7 lo)
__device__ unsigned char g_aimg[64 * 32 * 16384];
// B image: [z 3][n-panel 8][k-chunk 32][16KB]  (only hi chunks 0-3 used)
__device__ unsigned char g_bimg[3 * 8 * 32 * 16384];
// Q image: [bh 64][q-panel 16][32KB]  (hi 16KB then lo 16KB; 128 rows x 128B)
__device__ unsigned char g_qimg[64 * 16 * 32768];
// KV image: [bh 64][s-tile 32][32KB]  (Kh 8K | Kl 8K | Vh 8K | unused 8K)
__device__ unsigned char g_kvimg[64 * 32 * 32768];
__device__ float g_v[B_ * H_ * S_ * DH_];

#define SWZ(c, r) ((((c) ^ ((r) & 7)) << 4))

// ---------------- helpers ----------------------------------------------------
static __device__ __forceinline__ uint32_t s2u(const void* p) {
    uint32_t a;
    asm("{ .reg .u64 t; cvta.to.shared.u64 t, %1; cvt.u32.u64 %0, t; }"
        : "=r"(a) : "l"(p));
    return a;
}

static __device__ __forceinline__ void mbar_init(uint32_t a, uint32_t cnt) {
    asm volatile("mbarrier.init.shared.b64 [%0], %1;" :: "r"(a), "r"(cnt) : "memory");
}
static __device__ __forceinline__ void mbar_expect_tx(uint32_t a, uint32_t bytes) {
    asm volatile("mbarrier.arrive.expect_tx.shared.b64 _, [%0], %1;"
                 :: "r"(a), "r"(bytes) : "memory");
}
static __device__ __forceinline__ void mbar_wait(uint32_t a, uint32_t parity) {
    asm volatile(
        "{\n\t.reg .pred P;\n\t"
        "W_%=:\n\t"
        "mbarrier.try_wait.parity.shared::cta.b64 P, [%0], %1;\n\t"
        "@!P bra W_%=;\n\t}"
        :: "r"(a), "r"(parity) : "memory");
}
static __device__ __forceinline__ void bulk_g2s(uint32_t dst, const void* src,
                                                uint32_t bytes, uint32_t mbar) {
    asm volatile(
        "cp.async.bulk.shared::cluster.global.mbarrier::complete_tx::bytes "
        "[%0], [%1], %2, [%3];"
        :: "r"(dst), "l"(__cvta_generic_to_global(src)), "r"(bytes), "r"(mbar)
        : "memory");
}

#define LDSM4(r0, r1, r2, r3, a)                                            \
    asm volatile("ldmatrix.sync.aligned.m8n8.x4.shared.b16 "                \
                 "{%0,%1,%2,%3}, [%4];"                                     \
                 : "=r"(r0), "=r"(r1), "=r"(r2), "=r"(r3) : "r"(a))

#define MMA16816(d, a, b0v, b1v)                                            \
    asm volatile("mma.sync.aligned.m16n8k16.row.col.f32.f16.f16.f32 "       \
                 "{%0,%1,%2,%3}, {%4,%5,%6,%7}, {%8,%9}, {%0,%1,%2,%3};"    \
                 : "+f"((d)[0]), "+f"((d)[1]), "+f"((d)[2]), "+f"((d)[3])   \
                 : "r"((a)[0]), "r"((a)[1]), "r"((a)[2]), "r"((a)[3]),      \
                   "r"(b0v), "r"(b1v))

static __device__ __forceinline__ void hsplit(float v, __half& h, __half& l) {
    h = __float2half_rn(v);
    l = __float2half_rn(v - __half2float(h));
}

static __device__ __forceinline__ uint32_t pk(__half a, __half b) {
    return (uint32_t)__half_as_ushort(a) | ((uint32_t)__half_as_ushort(b) << 16);
}

static __device__ __forceinline__ void split2(float a, float b, uint32_t& hi, uint32_t& lo) {
    __half ha = __float2half_rn(a), hb = __float2half_rn(b);
    __half la = __float2half_rn(a - __half2float(ha));
    __half lb = __float2half_rn(b - __half2float(hb));
    hi = pk(ha, hb);
    lo = pk(la, lb);
}

// FFMA-only exp (no MUFU): exp(x) for x <= ~0, clamped at -87.
static __device__ __forceinline__ float fexp(float x) {
    x = fmaxf(x, -87.0f);
    float t = x * 1.4426950408889634f;
    float n = t + 12582912.0f;
    int   e = __float_as_int(n) - 0x4B400000;
    float fn = n - 12582912.0f;
    float f  = t - fn;
    float p = 0.0013333558f;
    p = fmaf(p, f, 0.0096181291f);
    p = fmaf(p, f, 0.0555041087f);
    p = fmaf(p, f, 0.2402265069f);
    p = fmaf(p, f, 0.6931471806f);
    p = fmaf(p, f, 1.0f);
    return p * __int_as_float((e + 127) << 23);
}

// ---------------------------------------------------------------------------
// Preprocessing: split X into fp16 hi/lo, writing the A tile image.
// ---------------------------------------------------------------------------
__global__ void xsplit(const float* __restrict__ x)
{
    int i = blockIdx.x * 256 + threadIdx.x;      // 8-float chunk index
    int l = i * 8;
    int m = l >> 10, k = l & (D_ - 1);
    float4 v0 = ((const float4*)x)[2 * i];
    float4 v1 = ((const float4*)x)[2 * i + 1];
    float vv[8] = {v0.x, v0.y, v0.z, v0.w, v1.x, v1.y, v1.z, v1.w};
    __half hi[8], lo[8];
    #pragma unroll
    for (int j = 0; j < 8; j++) hsplit(vv[j], hi[j], lo[j]);
    uint4 h4 = make_uint4(pk(hi[0], hi[1]), pk(hi[2], hi[3]), pk(hi[4], hi[5]), pk(hi[6], hi[7]));
    uint4 l4 = make_uint4(pk(lo[0], lo[1]), pk(lo[2], lo[3]), pk(lo[4], lo[5]), pk(lo[6], lo[7]));
    size_t base = ((size_t)(m >> 7) * 32 + (k >> 5)) * 16384;
    int r = m & 127, c = (k >> 3) & 3;
    *(uint4*)&g_aimg[base + r * 128 + SWZ(c, r)]     = h4;
    *(uint4*)&g_aimg[base + r * 128 + SWZ(c + 4, r)] = l4;
}

// ---------------------------------------------------------------------------
// Preprocessing: transpose W, fp16 round, write B tile image (hi only).
// ---------------------------------------------------------------------------
__global__ void wsplit(const float* __restrict__ Wq,
                       const float* __restrict__ Wk,
                       const float* __restrict__ Wv)
{
    __shared__ float t[32][33];
    const int z = blockIdx.z;
    const float* W = (z == 0) ? Wq : (z == 1) ? Wk : Wv;
    const int n  = blockIdx.x * 32 + threadIdx.x;
    const int k0 = blockIdx.y * 32;
    #pragma unroll
    for (int dy = 0; dy < 32; dy += 8) {
        int k = k0 + threadIdx.y + dy;
        t[threadIdx.y + dy][threadIdx.x] = W[(size_t)k * D_ + n];
    }
    __syncthreads();
    const int kk = k0 + threadIdx.x;
    #pragma unroll
    for (int dy = 0; dy < 32; dy += 8) {
        int nn = blockIdx.x * 32 + threadIdx.y + dy;
        float v = t[threadIdx.x][threadIdx.y + dy];
        size_t base = ((size_t)(z * 8 + (nn >> 7)) * 32 + (kk >> 5)) * 16384;
        int r = nn & 127, c = (kk >> 3) & 3, byb = (kk & 7) * 2;
        *(unsigned short*)&g_bimg[base + r * 128 + SWZ(c, r) + byb] =
            __half_as_ushort(__float2half_rn(v));
    }
}

// ---------------------------------------------------------------------------
// QKV GEMM: 2-term fp16 split (A exact hi+lo, B hi only).  bulk-copy staged.
// ---------------------------------------------------------------------------
#define NK     32
#define SMEM_G (1024 + 3 * 32768)

__global__ __launch_bounds__(256) void qkv_gemm_mma()
{
    extern __shared__ char smem[];
    const uint32_t sb = s2u(smem);
    const int tid  = threadIdx.x;
    const int warp = tid >> 5;
    const int lane = tid & 31;
    const int wm   = warp & 1;
    const int wn   = warp >> 1;

    const int n0 = blockIdx.x * 128;
    const int m0 = blockIdx.y * 128;
    const int z  = blockIdx.z;

    if (tid == 0) {
        mbar_init(sb + 0, 1);
        mbar_init(sb + 8, 1);
        mbar_init(sb + 16, 1);
    }
    __syncthreads();

    const unsigned char* Asrc = g_aimg + (size_t)blockIdx.y * 32 * 16384;
    const unsigned char* Bsrc = g_bimg + (size_t)(z * 8 + blockIdx.x) * 32 * 16384;

    if (tid == 0) {
        #pragma unroll
        for (int s = 0; s < 3; s++) {
            mbar_expect_tx(sb + 8 * s, 32768);
            bulk_g2s(sb + 1024 + s * 32768,         Asrc + s * 16384, 16384, sb + 8 * s);
            bulk_g2s(sb + 1024 + s * 32768 + 16384, Bsrc + s * 16384, 16384, sb + 8 * s);
        }
    }

    float acc[4][4][4];
    #pragma unroll
    for (int mi = 0; mi < 4; mi++)
        #pragma unroll
        for (int ni = 0; ni < 4; ni++)
            #pragma unroll
            for (int r = 0; r < 4; r++) acc[mi][ni][r] = 0.f;

    int aRow[4];
    #pragma unroll
    for (int mi = 0; mi < 4; mi++) aRow[mi] = wm * 64 + mi * 16 + (lane & 15);
    const int aG = (lane >> 4);
    int bRow[2];
    #pragma unroll
    for (int p = 0; p < 2; p++) bRow[p] = wn * 32 + p * 16 + (lane & 7) + ((lane & 16) >> 1);
    const int bG = (lane >> 3) & 1;

    for (int i = 0; i < NK; i++) {
        const int s = i % 3;
        const uint32_t parity = (uint32_t)((i / 3) & 1);
        mbar_wait(sb + 8 * s, parity);

        const uint32_t aBase = sb + 1024 + s * 32768;
        const uint32_t bBase = aBase + 16384;

        #pragma unroll
        for (int kstep = 0; kstep < 2; kstep++) {
            const int g0 = kstep * 2;

            uint32_t ah[4][4], bh2[2][4];
            #pragma unroll
            for (int mi = 0; mi < 4; mi++) {
                int r = aRow[mi];
                uint32_t ad = aBase + r * 128 + (((g0 + aG) ^ (r & 7)) << 4);
                LDSM4(ah[mi][0], ah[mi][1], ah[mi][2], ah[mi][3], ad);
            }
            #pragma unroll
            for (int p = 0; p < 2; p++) {
                int r = bRow[p];
                uint32_t bd = bBase + r * 128 + (((g0 + bG) ^ (r & 7)) << 4);
                LDSM4(bh2[p][0], bh2[p][1], bh2[p][2], bh2[p][3], bd);
            }
            #pragma unroll
            for (int mi = 0; mi < 4; mi++)
                #pragma unroll
                for (int ni = 0; ni < 4; ni++)
                    MMA16816(acc[mi][ni], ah[mi], bh2[ni >> 1][(ni & 1) * 2], bh2[ni >> 1][(ni & 1) * 2 + 1]);

            // term 2: Al * Bh
            {
                uint32_t al[4][4];
                #pragma unroll
                for (int mi = 0; mi < 4; mi++) {
                    int r = aRow[mi];
                    uint32_t ad = aBase + r * 128 + ((((4 + g0 + aG)) ^ (r & 7)) << 4);
                    LDSM4(al[mi][0], al[mi][1], al[mi][2], al[mi][3], ad);
                }
                #pragma unroll
                for (int mi = 0; mi < 4; mi++)
                    #pragma unroll
                    for (int ni = 0; ni < 4; ni++)
                        MMA16816(acc[mi][ni], al[mi], bh2[ni >> 1][(ni & 1) * 2], bh2[ni >> 1][(ni & 1) * 2 + 1]);
            }
        }

        __syncthreads();
        const int nx = i + 3;
        if (nx < NK && tid == 0) {
            mbar_expect_tx(sb + 8 * s, 32768);
            bulk_g2s(aBase, Asrc + nx * 16384, 16384, sb + 8 * s);
            bulk_g2s(bBase, Bsrc + nx * 16384, 16384, sb + 8 * s);
        }
    }

    // epilogue: z=0 -> Q image; z=1 -> K part of KV image; z=2 -> V fp32
    #pragma unroll
    for (int mi = 0; mi < 4; mi++) {
        #pragma unroll
        for (int ni = 0; ni < 4; ni++) {
            int m = m0 + wm * 64 + mi * 16 + (lane >> 2);
            int n = n0 + wn * 32 + ni * 8 + ((lane & 3) << 1);
            int h  = n >> 6;
            int dh = n & (DH_ - 1);
            #pragma unroll
            for (int half = 0; half < 2; half++) {
                int mm = m + half * 8;
                int b  = mm >> 11;
                int sq = mm & (S_ - 1);
                float v0 = acc[mi][ni][half * 2];
                float v1 = acc[mi][ni][half * 2 + 1];
                if (z == 2) {
                    *(float2*)&g_v[(((size_t)(b * H_ + h) * S_ + sq) * DH_) + dh] =
                        make_float2(v0, v1);
                } else {
                    __half h0, l0, h1, l1;
                    hsplit(v0, h0, l0); hsplit(v1, h1, l1);
                    size_t bh = (size_t)b * H_ + h;
                    if (z == 0) {
                        size_t ob = (bh * 16 + (sq >> 7)) * 32768
                                  + (size_t)(sq & 127) * 128
                                  + SWZ(dh >> 3, sq & 127) + (dh & 7) * 2;
                        *(uint32_t*)&g_qimg[ob]         = pk(h0, h1);
                        *(uint32_t*)&g_qimg[ob + 16384] = pk(l0, l1);
                    } else {
                        size_t ob = (bh * 32 + (sq >> 6)) * 32768
                                  + (size_t)(sq & 63) * 128
                                  + SWZ(dh >> 3, sq & 63) + (dh & 7) * 2;
                        *(uint32_t*)&g_kvimg[ob]        = pk(h0, h1);
                        *(uint32_t*)&g_kvimg[ob + 8192] = pk(l0, l1);
                    }
                }
            }
        }
    }
}

// ---------------------------------------------------------------------------
// V transpose: fp16 round, write Vh only into KV image (+16384).
// ---------------------------------------------------------------------------
__global__ __launch_bounds__(256) void vtrans()
{
    __shared__ float t[64][65];
    const int b = blockIdx.z, h = blockIdx.y;
    const int s0 = blockIdx.x * 64;
    const int tid = threadIdx.x;
    const size_t bh = (size_t)b * H_ + h;
    const size_t base_in = (bh * S_ + s0) * DH_;
    #pragma unroll
    for (int i = 0; i < 16; i++) {
        int idx = tid + i * 256;
        int sl = idx >> 6, dh = idx & 63;
        t[sl][dh] = g_v[base_in + (size_t)sl * DH_ + dh];
    }
    __syncthreads();
    const size_t base = (bh * 32 + blockIdx.x) * 32768 + 16384;
    #pragma unroll
    for (int i = 0; i < 8; i++) {
        int idx = (tid + i * 256) * 2;
        int dh = idx >> 6, sl = idx & 63;       // sl even
        __half ha = __float2half_rn(t[sl][dh]);
        __half hb = __float2half_rn(t[sl + 1][dh]);
        uint32_t off = dh * 128 + SWZ((sl >> 3) & 7, dh) + (sl & 7) * 2;
        *(uint32_t*)&g_kvimg[base + off] = pk(ha, hb);
    }
}

// ---------------------------------------------------------------------------
// Tensor-core flash attention: S 3-term (exact), PV 2-term (P split, Vh only).
// ---------------------------------------------------------------------------
#define NKT    32
#define SMEM_A (1024 + 3 * 32768)
#define OFF_Q  (1024 + 65536)

__global__ __launch_bounds__(256) void attn_mma(float* __restrict__ out)
{
    extern __shared__ char sm[];
    const uint32_t sb = s2u(sm);
    const int tid = threadIdx.x, warp = tid >> 5, lane = tid & 31;
    const int b = blockIdx.z, h = blockIdx.y, q0 = blockIdx.x * 128;
    const size_t bh = (size_t)(b * H_ + h);

    const unsigned char* Qsrc  = g_qimg + (bh * 16 + blockIdx.x) * 32768;
    const unsigned char* KVsrc = g_kvimg + bh * 32 * 32768;

    if (tid == 0) {
        mbar_init(sb + 0, 1);      // Q
        mbar_init(sb + 8, 1);      // KV stage 0
        mbar_init(sb + 16, 1);     // KV stage 1
    }
    __syncthreads();

    if (tid == 0) {
        mbar_expect_tx(sb, 32768);
        bulk_g2s(sb + OFF_Q, Qsrc, 32768, sb);
        mbar_expect_tx(sb + 8, 24576);
        bulk_g2s(sb + 1024, KVsrc, 24576, sb + 8);
    }

    mbar_wait(sb, 0);

    uint32_t Qh[4][4], Ql[4][4];
    {
        const int ar = warp * 16 + (lane & 15);
        const int ag = lane >> 4;
        #pragma unroll
        for (int kc = 0; kc < 4; kc++) {
            uint32_t ad = sb + OFF_Q + ar * 128 + (((kc * 2 + ag) ^ (ar & 7)) << 4);
            LDSM4(Qh[kc][0], Qh[kc][1], Qh[kc][2], Qh[kc][3], ad);
            ad += 16384;
            LDSM4(Ql[kc][0], Ql[kc][1], Ql[kc][2], Ql[kc][3], ad);
        }
    }

    float o[8][4];
    #pragma unroll
    for (int j = 0; j < 8; j++)
        #pragma unroll
        for (int r = 0; r < 4; r++) o[j][r] = 0.f;
    float m0 = -1e30f, m1 = -1e30f, l0 = 0.f, l1 = 0.f;

    const int brb = (lane & 7) + ((lane & 16) >> 1);
    const int bg  = (lane >> 3) & 1;

    for (int t = 0; t < NKT; t++) {
        if (t + 1 < NKT && tid == 0) {
            const int st = (t + 1) & 1;
            mbar_expect_tx(sb + 8 + 8 * st, 24576);
            bulk_g2s(sb + 1024 + st * 32768, KVsrc + (size_t)(t + 1) * 32768,
                     24576, sb + 8 + 8 * st);
        }
        mbar_wait(sb + 8 + 8 * (t & 1), (uint32_t)((t >> 1) & 1));

        const uint32_t kvb = sb + 1024 + (t & 1) * 32768;

        // ---- S = Q K^T (3 terms: Qh*Kh + Ql*Kh + Qh*Kl) ----
        float s[8][4];
        #pragma unroll
        for (int j = 0; j < 8; j++)
            #pragma unroll
            for (int r = 0; r < 4; r++) s[j][r] = 0.f;

        #pragma unroll
        for (int kc = 0; kc < 4; kc++) {
            const int g = kc * 2 + bg;
            uint32_t kf[4][4], lf[4][4];
            #pragma unroll
            for (int nt = 0; nt < 4; nt++) {
                int r = nt * 16 + brb;
                uint32_t off = r * 128 + ((g ^ (r & 7)) << 4);
                LDSM4(kf[nt][0], kf[nt][1], kf[nt][2], kf[nt][3], kvb + off);
                LDSM4(lf[nt][0], lf[nt][1], lf[nt][2], lf[nt][3], kvb + 8192 + off);
            }
            #pragma unroll
            for (int nt = 0; nt < 4; nt++)
                #pragma unroll
                for (int h2 = 0; h2 < 2; h2++) {
                    int ni = nt * 2 + h2;
                    MMA16816(s[ni], Qh[kc], kf[nt][h2 * 2], kf[nt][h2 * 2 + 1]);
                    MMA16816(s[ni], Ql[kc], kf[nt][h2 * 2], kf[nt][h2 * 2 + 1]);
                    MMA16816(s[ni], Qh[kc], lf[nt][h2 * 2], lf[nt][h2 * 2 + 1]);
                }
        }

        // ---- online softmax ----
        float mt0 = -1e30f, mt1 = -1e30f;
        #pragma unroll
        for (int j = 0; j < 8; j++) {
            mt0 = fmaxf(mt0, fmaxf(s[j][0], s[j][1]));
            mt1 = fmaxf(mt1, fmaxf(s[j][2], s[j][3]));
        }
        mt0 *= 0.0625f; mt1 *= 0.0625f;
        mt0 = fmaxf(mt0, __shfl_xor_sync(0xFFFFFFFFu, mt0, 1));
        mt0 = fmaxf(mt0, __shfl_xor_sync(0xFFFFFFFFu, mt0, 2));
        mt1 = fmaxf(mt1, __shfl_xor_sync(0xFFFFFFFFu, mt1, 1));
        mt1 = fmaxf(mt1, __shfl_xor_sync(0xFFFFFFFFu, mt1, 2));
        const float mn0 = fmaxf(m0, mt0), mn1 = fmaxf(m1, mt1);
        const float sc0 = fexp(m0 - mn0), sc1 = fexp(m1 - mn1);
        m0 = mn0; m1 = mn1;
        l0 *= sc0; l1 *= sc1;
        #pragma unroll
        for (int j = 0; j < 8; j++) {
            o[j][0] *= sc0; o[j][1] *= sc0;
            o[j][2] *= sc1; o[j][3] *= sc1;
        }
        #pragma unroll
        for (int j = 0; j < 8; j++) {
            float p0 = fexp(fmaf(s[j][0], 0.0625f, -mn0));
            float p1 = fexp(fmaf(s[j][1], 0.0625f, -mn0));
            float p2 = fexp(fmaf(s[j][2], 0.0625f, -mn1));
            float p3 = fexp(fmaf(s[j][3], 0.0625f, -mn1));
            l0 += p0 + p1; l1 += p2 + p3;
            s[j][0] = p0; s[j][1] = p1; s[j][2] = p2; s[j][3] = p3;
        }

        // ---- O += P V (2 terms: Ph*Vh + Pl*Vh) ----
        #pragma unroll
        for (int kc = 0; kc < 4; kc++) {
            const int g = kc * 2 + bg;
            uint32_t vh4[4][4];
            #pragma unroll
            for (int nt = 0; nt < 4; nt++) {
                int r = nt * 16 + brb;
                uint32_t off = r * 128 + ((g ^ (r & 7)) << 4);
                LDSM4(vh4[nt][0], vh4[nt][1], vh4[nt][2], vh4[nt][3], kvb + 16384 + off);
            }
            uint32_t Ahf[4], Alf[4];
            split2(s[2 * kc][0],     s[2 * kc][1],     Ahf[0], Alf[0]);
            split2(s[2 * kc][2],     s[2 * kc][3],     Ahf[1], Alf[1]);
            split2(s[2 * kc + 1][0], s[2 * kc + 1][1], Ahf[2], Alf[2]);
            split2(s[2 * kc + 1][2], s[2 * kc + 1][3], Ahf[3], Alf[3]);
            #pragma unroll
            for (int nt = 0; nt < 4; nt++)
                #pragma unroll
                for (int h2 = 0; h2 < 2; h2++) {
                    int ni = nt * 2 + h2;
                    MMA16816(o[ni], Ahf, vh4[nt][h2 * 2], vh4[nt][h2 * 2 + 1]);
                    MMA16816(o[ni], Alf, vh4[nt][h2 * 2], vh4[nt][h2 * 2 + 1]);
                }
        }
        __syncthreads();
    }

    // ---- epilogue ----
    l0 += __shfl_xor_sync(0xFFFFFFFFu, l0, 1);
    l0 += __shfl_xor_sync(0xFFFFFFFFu, l0, 2);
    l1 += __shfl_xor_sync(0xFFFFFFFFu, l1, 1);
    l1 += __shfl_xor_sync(0xFFFFFFFFu, l1, 2);
    const float i0 = 1.0f / l0, i1 = 1.0f / l1;

    const int q = q0 + warp * 16 + (lane >> 2);
    float* op = out + ((size_t)b * S_ + q) * D_ + h * DH_;
    #pragma unroll
    for (int j = 0; j < 8; j++) {
        int dh = j * 8 + ((lane & 3) << 1);
        *(float2*)(op + dh)          = make_float2(o[j][0] * i0, o[j][1] * i0);
        *(float2*)(op + 8 * D_ + dh) = make_float2(o[j][2] * i1, o[j][3] * i1);
    }
}

// ---------------------------------------------------------------------------
// Launch
// ---------------------------------------------------------------------------
extern "C" void kernel_launch(void* const* d_in, const int* in_sizes, int n_in,
                              void* d_out, int out_size)
{
    const float* x  = (const float*)d_in[0];
    const float* wq = (const float*)d_in[1];
    const float* wk = (const float*)d_in[2];
    const float* wv = (const float*)d_in[3];
    float* out = (float*)d_out;

    static bool attr_set = false;
    if (!attr_set) {
        cudaFuncSetAttribute(qkv_gemm_mma,
                             cudaFuncAttributeMaxDynamicSharedMemorySize, SMEM_G);
        cudaFuncSetAttribute(attn_mma,
                             cudaFuncAttributeMaxDynamicSharedMemorySize, SMEM_A);
        attr_set = true;
    }

    xsplit<<<(M_ * D_ / 8) / 256, 256>>>(x);
    wsplit<<<dim3(32, 32, 3), dim3(32, 8)>>>(wq, wk, wv);
    qkv_gemm_mma<<<dim3(D_ / 128, M_ / 128, 3), 256, SMEM_G>>>();
    vtrans<<<dim3(S_ / 64, H_, B_), 256>>>();
    attn_mma<<<dim3(S_ / 128, H_, B_), 256, SMEM_A>>>(out);
}

// round 7
// speedup vs baseline: 6.4603x; 1.4402x over previous
#include <cuda_runtime.h>
#include <cuda_fp16.h>
#include <cstdint>

#define B_  4
#define S_  2048
#define D_  1024
#define H_  16
#define DH_ 64
#define M_  (B_ * S_)   // 8192

// ---------------- device scratch: pre-swizzled tile images ------------------
// A image: [m-panel 64][k-chunk 32][16KB]  (128 rows x 128B; chunks 0-3 hi, 4-7 lo)
__device__ unsigned char g_aimg[64 * 32 * 16384];
// B image: [z 3][n-panel 8][k-chunk 32][16KB]  (hi only)
__device__ unsigned char g_bimg[3 * 8 * 32 * 16384];
// Q image: [bh 64][q-panel 16][32KB]  (hi 16KB then lo 16KB; 128 rows x 128B)
__device__ unsigned char g_qimg[64 * 16 * 32768];
// KV image: [bh 64][s-tile 32][24KB]  (Kh 8K | Kl 8K | Vh 8K)
__device__ unsigned char g_kvimg[64 * 32 * 24576];
__device__ float g_v[B_ * H_ * S_ * DH_];

#define KVSTRIDE 24576

#define SWZ(c, r) ((((c) ^ ((r) & 7)) << 4))

// ---------------- helpers ----------------------------------------------------
static __device__ __forceinline__ uint32_t s2u(const void* p) {
    uint32_t a;
    asm("{ .reg .u64 t; cvta.to.shared.u64 t, %1; cvt.u32.u64 %0, t; }"
        : "=r"(a) : "l"(p));
    return a;
}

static __device__ __forceinline__ void mbar_init(uint32_t a, uint32_t cnt) {
    asm volatile("mbarrier.init.shared.b64 [%0], %1;" :: "r"(a), "r"(cnt) : "memory");
}
static __device__ __forceinline__ void mbar_expect_tx(uint32_t a, uint32_t bytes) {
    asm volatile("mbarrier.arrive.expect_tx.shared.b64 _, [%0], %1;"
                 :: "r"(a), "r"(bytes) : "memory");
}
static __device__ __forceinline__ void mbar_wait(uint32_t a, uint32_t parity) {
    asm volatile(
        "{\n\t.reg .pred P;\n\t"
        "W_%=:\n\t"
        "mbarrier.try_wait.parity.shared::cta.b64 P, [%0], %1;\n\t"
        "@!P bra W_%=;\n\t}"
        :: "r"(a), "r"(parity) : "memory");
}
static __device__ __forceinline__ void bulk_g2s(uint32_t dst, const void* src,
                                                uint32_t bytes, uint32_t mbar) {
    asm volatile(
        "cp.async.bulk.shared::cluster.global.mbarrier::complete_tx::bytes "
        "[%0], [%1], %2, [%3];"
        :: "r"(dst), "l"(__cvta_generic_to_global(src)), "r"(bytes), "r"(mbar)
        : "memory");
}

#define LDSM4(r0, r1, r2, r3, a)                                            \
    asm volatile("ldmatrix.sync.aligned.m8n8.x4.shared.b16 "                \
                 "{%0,%1,%2,%3}, [%4];"                                     \
                 : "=r"(r0), "=r"(r1), "=r"(r2), "=r"(r3) : "r"(a))

#define MMA16816(d, a, b0v, b1v)                                            \
    asm volatile("mma.sync.aligned.m16n8k16.row.col.f32.f16.f16.f32 "       \
                 "{%0,%1,%2,%3}, {%4,%5,%6,%7}, {%8,%9}, {%0,%1,%2,%3};"    \
                 : "+f"((d)[0]), "+f"((d)[1]), "+f"((d)[2]), "+f"((d)[3])   \
                 : "r"((a)[0]), "r"((a)[1]), "r"((a)[2]), "r"((a)[3]),      \
                   "r"(b0v), "r"(b1v))

static __device__ __forceinline__ void hsplit(float v, __half& h, __half& l) {
    h = __float2half_rn(v);
    l = __float2half_rn(v - __half2float(h));
}

static __device__ __forceinline__ uint32_t pk(__half a, __half b) {
    return (uint32_t)__half_as_ushort(a) | ((uint32_t)__half_as_ushort(b) << 16);
}

static __device__ __forceinline__ uint32_t pkf(float a, float b) {
    __half2 h = __floats2half2_rn(a, b);
    return *(uint32_t*)&h;
}

// ---------------------------------------------------------------------------
// Preprocessing: split X into fp16 hi/lo, writing the A tile image.
// ---------------------------------------------------------------------------
__global__ void xsplit(const float* __restrict__ x)
{
    int i = blockIdx.x * 256 + threadIdx.x;      // 8-float chunk index
    int l = i * 8;
    int m = l >> 10, k = l & (D_ - 1);
    float4 v0 = ((const float4*)x)[2 * i];
    float4 v1 = ((const float4*)x)[2 * i + 1];
    float vv[8] = {v0.x, v0.y, v0.z, v0.w, v1.x, v1.y, v1.z, v1.w};
    __half hi[8], lo[8];
    #pragma unroll
    for (int j = 0; j < 8; j++) hsplit(vv[j], hi[j], lo[j]);
    uint4 h4 = make_uint4(pk(hi[0], hi[1]), pk(hi[2], hi[3]), pk(hi[4], hi[5]), pk(hi[6], hi[7]));
    uint4 l4 = make_uint4(pk(lo[0], lo[1]), pk(lo[2], lo[3]), pk(lo[4], lo[5]), pk(lo[6], lo[7]));
    size_t base = ((size_t)(m >> 7) * 32 + (k >> 5)) * 16384;
    int r = m & 127, c = (k >> 3) & 3;
    *(uint4*)&g_aimg[base + r * 128 + SWZ(c, r)]     = h4;
    *(uint4*)&g_aimg[base + r * 128 + SWZ(c + 4, r)] = l4;
}

// ---------------------------------------------------------------------------
// Preprocessing: transpose W, fp16 round, write B tile image (hi only).
// ---------------------------------------------------------------------------
__global__ void wsplit(const float* __restrict__ Wq,
                       const float* __restrict__ Wk,
                       const float* __restrict__ Wv)
{
    __shared__ float t[32][33];
    const int z = blockIdx.z;
    const float* W = (z == 0) ? Wq : (z == 1) ? Wk : Wv;
    const int n  = blockIdx.x * 32 + threadIdx.x;
    const int k0 = blockIdx.y * 32;
    #pragma unroll
    for (int dy = 0; dy < 32; dy += 8) {
        int k = k0 + threadIdx.y + dy;
        t[threadIdx.y + dy][threadIdx.x] = W[(size_t)k * D_ + n];
    }
    __syncthreads();
    const int kk = k0 + threadIdx.x;
    #pragma unroll
    for (int dy = 0; dy < 32; dy += 8) {
        int nn = blockIdx.x * 32 + threadIdx.y + dy;
        float v = t[threadIdx.x][threadIdx.y + dy];
        size_t base = ((size_t)(z * 8 + (nn >> 7)) * 32 + (kk >> 5)) * 16384;
        int r = nn & 127, c = (kk >> 3) & 3, byb = (kk & 7) * 2;
        *(unsigned short*)&g_bimg[base + r * 128 + SWZ(c, r) + byb] =
            __half_as_ushort(__float2half_rn(v));
    }
}

// ---------------------------------------------------------------------------
// QKV GEMM: 2-term fp16 split (A exact hi+lo, B hi only).  bulk-copy staged.
// ---------------------------------------------------------------------------
#define NK     32
#define SMEM_G (1024 + 3 * 32768)

__global__ __launch_bounds__(256, 2) void qkv_gemm_mma()
{
    extern __shared__ char smem[];
    const uint32_t sb = s2u(smem);
    const int tid  = threadIdx.x;
    const int warp = tid >> 5;
    const int lane = tid & 31;
    const int wm   = warp & 1;
    const int wn   = warp >> 1;

    const int n0 = blockIdx.x * 128;
    const int m0 = blockIdx.y * 128;
    const int z  = blockIdx.z;

    if (tid == 0) {
        mbar_init(sb + 0, 1);
        mbar_init(sb + 8, 1);
        mbar_init(sb + 16, 1);
    }
    __syncthreads();

    const unsigned char* Asrc = g_aimg + (size_t)blockIdx.y * 32 * 16384;
    const unsigned char* Bsrc = g_bimg + (size_t)(z * 8 + blockIdx.x) * 32 * 16384;

    if (tid == 0) {
        #pragma unroll
        for (int s = 0; s < 3; s++) {
            mbar_expect_tx(sb + 8 * s, 32768);
            bulk_g2s(sb + 1024 + s * 32768,         Asrc + s * 16384, 16384, sb + 8 * s);
            bulk_g2s(sb + 1024 + s * 32768 + 16384, Bsrc + s * 16384, 16384, sb + 8 * s);
        }
    }

    float acc[4][4][4];
    #pragma unroll
    for (int mi = 0; mi < 4; mi++)
        #pragma unroll
        for (int ni = 0; ni < 4; ni++)
            #pragma unroll
            for (int r = 0; r < 4; r++) acc[mi][ni][r] = 0.f;

    int aRow[4];
    #pragma unroll
    for (int mi = 0; mi < 4; mi++) aRow[mi] = wm * 64 + mi * 16 + (lane & 15);
    const int aG = (lane >> 4);
    int bRow[2];
    #pragma unroll
    for (int p = 0; p < 2; p++) bRow[p] = wn * 32 + p * 16 + (lane & 7) + ((lane & 16) >> 1);
    const int bG = (lane >> 3) & 1;

    for (int i = 0; i < NK; i++) {
        const int s = i % 3;
        const uint32_t parity = (uint32_t)((i / 3) & 1);
        mbar_wait(sb + 8 * s, parity);

        const uint32_t aBase = sb + 1024 + s * 32768;
        const uint32_t bBase = aBase + 16384;

        #pragma unroll
        for (int kstep = 0; kstep < 2; kstep++) {
            const int g0 = kstep * 2;

            uint32_t ah[4][4], bh2[2][4];
            #pragma unroll
            for (int mi = 0; mi < 4; mi++) {
                int r = aRow[mi];
                uint32_t ad = aBase + r * 128 + (((g0 + aG) ^ (r & 7)) << 4);
                LDSM4(ah[mi][0], ah[mi][1], ah[mi][2], ah[mi][3], ad);
            }
            #pragma unroll
            for (int p = 0; p < 2; p++) {
                int r = bRow[p];
                uint32_t bd = bBase + r * 128 + (((g0 + bG) ^ (r & 7)) << 4);
                LDSM4(bh2[p][0], bh2[p][1], bh2[p][2], bh2[p][3], bd);
            }
            #pragma unroll
            for (int mi = 0; mi < 4; mi++)
                #pragma unroll
                for (int ni = 0; ni < 4; ni++)
                    MMA16816(acc[mi][ni], ah[mi], bh2[ni >> 1][(ni & 1) * 2], bh2[ni >> 1][(ni & 1) * 2 + 1]);

            // term 2: Al * Bh
            {
                uint32_t al[4][4];
                #pragma unroll
                for (int mi = 0; mi < 4; mi++) {
                    int r = aRow[mi];
                    uint32_t ad = aBase + r * 128 + ((((4 + g0 + aG)) ^ (r & 7)) << 4);
                    LDSM4(al[mi][0], al[mi][1], al[mi][2], al[mi][3], ad);
                }
                #pragma unroll
                for (int mi = 0; mi < 4; mi++)
                    #pragma unroll
                    for (int ni = 0; ni < 4; ni++)
                        MMA16816(acc[mi][ni], al[mi], bh2[ni >> 1][(ni & 1) * 2], bh2[ni >> 1][(ni & 1) * 2 + 1]);
            }
        }

        __syncthreads();
        const int nx = i + 3;
        if (nx < NK && tid == 0) {
            mbar_expect_tx(sb + 8 * s, 32768);
            bulk_g2s(aBase, Asrc + nx * 16384, 16384, sb + 8 * s);
            bulk_g2s(bBase, Bsrc + nx * 16384, 16384, sb + 8 * s);
        }
    }

    // epilogue: z=0 -> Q image; z=1 -> K part of KV image; z=2 -> V fp32
    #pragma unroll
    for (int mi = 0; mi < 4; mi++) {
        #pragma unroll
        for (int ni = 0; ni < 4; ni++) {
            int m = m0 + wm * 64 + mi * 16 + (lane >> 2);
            int n = n0 + wn * 32 + ni * 8 + ((lane & 3) << 1);
            int h  = n >> 6;
            int dh = n & (DH_ - 1);
            #pragma unroll
            for (int half = 0; half < 2; half++) {
                int mm = m + half * 8;
                int b  = mm >> 11;
                int sq = mm & (S_ - 1);
                float v0 = acc[mi][ni][half * 2];
                float v1 = acc[mi][ni][half * 2 + 1];
                if (z == 2) {
                    *(float2*)&g_v[(((size_t)(b * H_ + h) * S_ + sq) * DH_) + dh] =
                        make_float2(v0, v1);
                } else {
                    __half h0, l0, h1, l1;
                    hsplit(v0, h0, l0); hsplit(v1, h1, l1);
                    size_t bh = (size_t)b * H_ + h;
                    if (z == 0) {
                        size_t ob = (bh * 16 + (sq >> 7)) * 32768
                                  + (size_t)(sq & 127) * 128
                                  + SWZ(dh >> 3, sq & 127) + (dh & 7) * 2;
                        *(uint32_t*)&g_qimg[ob]         = pk(h0, h1);
                        *(uint32_t*)&g_qimg[ob + 16384] = pk(l0, l1);
                    } else {
                        size_t ob = (bh * 32 + (sq >> 6)) * (size_t)KVSTRIDE
                                  + (size_t)(sq & 63) * 128
                                  + SWZ(dh >> 3, sq & 63) + (dh & 7) * 2;
                        *(uint32_t*)&g_kvimg[ob]        = pk(h0, h1);
                        *(uint32_t*)&g_kvimg[ob + 8192] = pk(l0, l1);
                    }
                }
            }
        }
    }
}

// ---------------------------------------------------------------------------
// V transpose: fp16 round, write Vh into KV image (+16384).
// ---------------------------------------------------------------------------
__global__ __launch_bounds__(256) void vtrans()
{
    __shared__ float t[64][65];
    const int b = blockIdx.z, h = blockIdx.y;
    const int s0 = blockIdx.x * 64;
    const int tid = threadIdx.x;
    const size_t bh = (size_t)b * H_ + h;
    const size_t base_in = (bh * S_ + s0) * DH_;
    #pragma unroll
    for (int i = 0; i < 16; i++) {
        int idx = tid + i * 256;
        int sl = idx >> 6, dh = idx & 63;
        t[sl][dh] = g_v[base_in + (size_t)sl * DH_ + dh];
    }
    __syncthreads();
    const size_t base = (bh * 32 + blockIdx.x) * (size_t)KVSTRIDE + 16384;
    #pragma unroll
    for (int i = 0; i < 8; i++) {
        int idx = (tid + i * 256) * 2;
        int dh = idx >> 6, sl = idx & 63;       // sl even
        __half ha = __float2half_rn(t[sl][dh]);
        __half hb = __float2half_rn(t[sl + 1][dh]);
        uint32_t off = dh * 128 + SWZ((sl >> 3) & 7, dh) + (sl & 7) * 2;
        *(uint32_t*)&g_kvimg[base + off] = pk(ha, hb);
    }
}

// ---------------------------------------------------------------------------
// Tensor-core flash attention: S 3-term (exact), PV 1-term (Ph * Vh).
// smem: mbars @ [0,1024); KV stage0 @1024 (24KB), stage1 @25600, Q @50176.
// ---------------------------------------------------------------------------
#define NKT    32
#define OFF_Q  (1024 + 2 * KVSTRIDE)
#define SMEM_A (OFF_Q + 32768)

__global__ __launch_bounds__(256) void attn_mma(float* __restrict__ out)
{
    extern __shared__ char sm[];
    const uint32_t sb = s2u(sm);
    const int tid = threadIdx.x, warp = tid >> 5, lane = tid & 31;
    const int b = blockIdx.z, h = blockIdx.y, q0 = blockIdx.x * 128;
    const size_t bh = (size_t)(b * H_ + h);

    const unsigned char* Qsrc  = g_qimg + (bh * 16 + blockIdx.x) * 32768;
    const unsigned char* KVsrc = g_kvimg + bh * 32 * (size_t)KVSTRIDE;

    if (tid == 0) {
        mbar_init(sb + 0, 1);      // Q
        mbar_init(sb + 8, 1);      // KV stage 0
        mbar_init(sb + 16, 1);     // KV stage 1
    }
    __syncthreads();

    if (tid == 0) {
        mbar_expect_tx(sb, 32768);
        bulk_g2s(sb + OFF_Q, Qsrc, 32768, sb);
        mbar_expect_tx(sb + 8, KVSTRIDE);
        bulk_g2s(sb + 1024, KVsrc, KVSTRIDE, sb + 8);
    }

    mbar_wait(sb, 0);

    uint32_t Qh[4][4], Ql[4][4];
    {
        const int ar = warp * 16 + (lane & 15);
        const int ag = lane >> 4;
        #pragma unroll
        for (int kc = 0; kc < 4; kc++) {
            uint32_t ad = sb + OFF_Q + ar * 128 + (((kc * 2 + ag) ^ (ar & 7)) << 4);
            LDSM4(Qh[kc][0], Qh[kc][1], Qh[kc][2], Qh[kc][3], ad);
            ad += 16384;
            LDSM4(Ql[kc][0], Ql[kc][1], Ql[kc][2], Ql[kc][3], ad);
        }
    }

    float o[8][4];
    #pragma unroll
    for (int j = 0; j < 8; j++)
        #pragma unroll
        for (int r = 0; r < 4; r++) o[j][r] = 0.f;
    float m0 = -1e30f, m1 = -1e30f, l0 = 0.f, l1 = 0.f;

    const int brb = (lane & 7) + ((lane & 16) >> 1);
    const int bg  = (lane >> 3) & 1;

    for (int t = 0; t < NKT; t++) {
        if (t + 1 < NKT && tid == 0) {
            const int st = (t + 1) & 1;
            mbar_expect_tx(sb + 8 + 8 * st, KVSTRIDE);
            bulk_g2s(sb + 1024 + st * KVSTRIDE, KVsrc + (size_t)(t + 1) * KVSTRIDE,
                     KVSTRIDE, sb + 8 + 8 * st);
        }
        mbar_wait(sb + 8 + 8 * (t & 1), (uint32_t)((t >> 1) & 1));

        const uint32_t kvb = sb + 1024 + (t & 1) * KVSTRIDE;

        // ---- S = Q K^T (3 terms: Qh*Kh + Ql*Kh + Qh*Kl) ----
        float s[8][4];
        #pragma unroll
        for (int j = 0; j < 8; j++)
            #pragma unroll
            for (int r = 0; r < 4; r++) s[j][r] = 0.f;

        #pragma unroll
        for (int kc = 0; kc < 4; kc++) {
            const int g = kc * 2 + bg;
            uint32_t kf[4][4], lf[4][4];
            #pragma unroll
            for (int nt = 0; nt < 4; nt++) {
                int r = nt * 16 + brb;
                uint32_t off = r * 128 + ((g ^ (r & 7)) << 4);
                LDSM4(kf[nt][0], kf[nt][1], kf[nt][2], kf[nt][3], kvb + off);
                LDSM4(lf[nt][0], lf[nt][1], lf[nt][2], lf[nt][3], kvb + 8192 + off);
            }
            #pragma unroll
            for (int nt = 0; nt < 4; nt++)
                #pragma unroll
                for (int h2 = 0; h2 < 2; h2++) {
                    int ni = nt * 2 + h2;
                    MMA16816(s[ni], Qh[kc], kf[nt][h2 * 2], kf[nt][h2 * 2 + 1]);
                    MMA16816(s[ni], Ql[kc], kf[nt][h2 * 2], kf[nt][h2 * 2 + 1]);
                    MMA16816(s[ni], Qh[kc], lf[nt][h2 * 2], lf[nt][h2 * 2 + 1]);
                }
        }

        // ---- online softmax (MUFU exp; conditional O rescale) ----
        float mt0 = -1e30f, mt1 = -1e30f;
        #pragma unroll
        for (int j = 0; j < 8; j++) {
            mt0 = fmaxf(mt0, fmaxf(s[j][0], s[j][1]));
            mt1 = fmaxf(mt1, fmaxf(s[j][2], s[j][3]));
        }
        mt0 *= 0.0625f; mt1 *= 0.0625f;
        mt0 = fmaxf(mt0, __shfl_xor_sync(0xFFFFFFFFu, mt0, 1));
        mt0 = fmaxf(mt0, __shfl_xor_sync(0xFFFFFFFFu, mt0, 2));
        mt1 = fmaxf(mt1, __shfl_xor_sync(0xFFFFFFFFu, mt1, 1));
        mt1 = fmaxf(mt1, __shfl_xor_sync(0xFFFFFFFFu, mt1, 2));
        const bool up0 = mt0 > m0, up1 = mt1 > m1;
        if (up0 | up1) {
            const float mn0 = up0 ? mt0 : m0;
            const float mn1 = up1 ? mt1 : m1;
            const float sc0 = __expf(m0 - mn0), sc1 = __expf(m1 - mn1);
            m0 = mn0; m1 = mn1;
            l0 *= sc0; l1 *= sc1;
            #pragma unroll
            for (int j = 0; j < 8; j++) {
                o[j][0] *= sc0; o[j][1] *= sc0;
                o[j][2] *= sc1; o[j][3] *= sc1;
            }
        }
        #pragma unroll
        for (int j = 0; j < 8; j++) {
            float p0 = __expf(fmaf(s[j][0], 0.0625f, -m0));
            float p1 = __expf(fmaf(s[j][1], 0.0625f, -m0));
            float p2 = __expf(fmaf(s[j][2], 0.0625f, -m1));
            float p3 = __expf(fmaf(s[j][3], 0.0625f, -m1));
            l0 += p0 + p1; l1 += p2 + p3;
            s[j][0] = p0; s[j][1] = p1; s[j][2] = p2; s[j][3] = p3;
        }

        // ---- O += P V (1 term: Ph * Vh) ----
        #pragma unroll
        for (int kc = 0; kc < 4; kc++) {
            const int g = kc * 2 + bg;
            uint32_t vh4[4][4];
            #pragma unroll
            for (int nt = 0; nt < 4; nt++) {
                int r = nt * 16 + brb;
                uint32_t off = r * 128 + ((g ^ (r & 7)) << 4);
                LDSM4(vh4[nt][0], vh4[nt][1], vh4[nt][2], vh4[nt][3], kvb + 16384 + off);
            }
            uint32_t Ahf[4];
            Ahf[0] = pkf(s[2 * kc][0],     s[2 * kc][1]);
            Ahf[1] = pkf(s[2 * kc][2],     s[2 * kc][3]);
            Ahf[2] = pkf(s[2 * kc + 1][0], s[2 * kc + 1][1]);
            Ahf[3] = pkf(s[2 * kc + 1][2], s[2 * kc + 1][3]);
            #pragma unroll
            for (int nt = 0; nt < 4; nt++)
                #pragma unroll
                for (int h2 = 0; h2 < 2; h2++) {
                    int ni = nt * 2 + h2;
                    MMA16816(o[ni], Ahf, vh4[nt][h2 * 2], vh4[nt][h2 * 2 + 1]);
                }
        }
        __syncthreads();
    }

    // ---- epilogue ----
    l0 += __shfl_xor_sync(0xFFFFFFFFu, l0, 1);
    l0 += __shfl_xor_sync(0xFFFFFFFFu, l0, 2);
    l1 += __shfl_xor_sync(0xFFFFFFFFu, l1, 1);
    l1 += __shfl_xor_sync(0xFFFFFFFFu, l1, 2);
    const float i0 = 1.0f / l0, i1 = 1.0f / l1;

    const int q = q0 + warp * 16 + (lane >> 2);
    float* op = out + ((size_t)b * S_ + q) * D_ + h * DH_;
    #pragma unroll
    for (int j = 0; j < 8; j++) {
        int dh = j * 8 + ((lane & 3) << 1);
        *(float2*)(op + dh)          = make_float2(o[j][0] * i0, o[j][1] * i0);
        *(float2*)(op + 8 * D_ + dh) = make_float2(o[j][2] * i1, o[j][3] * i1);
    }
}

// ---------------------------------------------------------------------------
// Launch
// ---------------------------------------------------------------------------
extern "C" void kernel_launch(void* const* d_in, const int* in_sizes, int n_in,
                              void* d_out, int out_size)
{
    const float* x  = (const float*)d_in[0];
    const float* wq = (const float*)d_in[1];
    const float* wk = (const float*)d_in[2];
    const float* wv = (const float*)d_in[3];
    float* out = (float*)d_out;

    static bool attr_set = false;
    if (!attr_set) {
        cudaFuncSetAttribute(qkv_gemm_mma,
                             cudaFuncAttributeMaxDynamicSharedMemorySize, SMEM_G);
        cudaFuncSetAttribute(attn_mma,
                             cudaFuncAttributeMaxDynamicSharedMemorySize, SMEM_A);
        attr_set = true;
    }

    xsplit<<<(M_ * D_ / 8) / 256, 256>>>(x);
    wsplit<<<dim3(32, 32, 3), dim3(32, 8)>>>(wq, wk, wv);
    qkv_gemm_mma<<<dim3(D_ / 128, M_ / 128, 3), 256, SMEM_G>>>();
    vtrans<<<dim3(S_ / 64, H_, B_), 256>>>();
    attn_mma<<<dim3(S_ / 128, H_, B_), 256, SMEM_A>>>(out);
}

// round 8
// speedup vs baseline: 11.2489x; 1.7412x over previous
#include <cuda_runtime.h>
#include <cuda_fp16.h>
#include <cstdint>

#define B_  4
#define S_  2048
#define D_  1024
#define H_  16
#define DH_ 64
#define M_  (B_ * S_)   // 8192

// ---------------- device scratch: pre-swizzled tile images (hi-only) --------
// A image: [m-panel 64][k-chunk 16][16KB]  (128 rows x 128B, k0..63 per chunk)
__device__ unsigned char g_aimg[64 * 16 * 16384];
// B image: [z 3][n-panel 8][k-chunk 16][16KB]
__device__ unsigned char g_bimg[3 * 8 * 16 * 16384];
// Q image: [bh 64][q-panel 16][16KB]  (128 rows x 128B, k = full DH)
__device__ unsigned char g_qimg[64 * 16 * 16384];
// KV image: [bh 64][s-tile 32][16KB]  (Kh 8K | Vh 8K; 64 rows x 128B)
__device__ unsigned char g_kvimg[64 * 32 * 16384];
__device__ float g_v[B_ * H_ * S_ * DH_];

#define KVSTRIDE 16384
#define SWZ(c, r) ((((c) ^ ((r) & 7)) << 4))

// ---------------- helpers ----------------------------------------------------
static __device__ __forceinline__ uint32_t s2u(const void* p) {
    uint32_t a;
    asm("{ .reg .u64 t; cvta.to.shared.u64 t, %1; cvt.u32.u64 %0, t; }"
        : "=r"(a) : "l"(p));
    return a;
}

static __device__ __forceinline__ void mbar_init(uint32_t a, uint32_t cnt) {
    asm volatile("mbarrier.init.shared.b64 [%0], %1;" :: "r"(a), "r"(cnt) : "memory");
}
static __device__ __forceinline__ void mbar_expect_tx(uint32_t a, uint32_t bytes) {
    asm volatile("mbarrier.arrive.expect_tx.shared.b64 _, [%0], %1;"
                 :: "r"(a), "r"(bytes) : "memory");
}
static __device__ __forceinline__ void mbar_wait(uint32_t a, uint32_t parity) {
    asm volatile(
        "{\n\t.reg .pred P;\n\t"
        "W_%=:\n\t"
        "mbarrier.try_wait.parity.shared::cta.b64 P, [%0], %1;\n\t"
        "@!P bra W_%=;\n\t}"
        :: "r"(a), "r"(parity) : "memory");
}
static __device__ __forceinline__ void bulk_g2s(uint32_t dst, const void* src,
                                                uint32_t bytes, uint32_t mbar) {
    asm volatile(
        "cp.async.bulk.shared::cluster.global.mbarrier::complete_tx::bytes "
        "[%0], [%1], %2, [%3];"
        :: "r"(dst), "l"(__cvta_generic_to_global(src)), "r"(bytes), "r"(mbar)
        : "memory");
}

#define LDSM4(r0, r1, r2, r3, a)                                            \
    asm volatile("ldmatrix.sync.aligned.m8n8.x4.shared.b16 "                \
                 "{%0,%1,%2,%3}, [%4];"                                     \
                 : "=r"(r0), "=r"(r1), "=r"(r2), "=r"(r3) : "r"(a))

#define MMA16816(d, a, b0v, b1v)                                            \
    asm volatile("mma.sync.aligned.m16n8k16.row.col.f32.f16.f16.f32 "       \
                 "{%0,%1,%2,%3}, {%4,%5,%6,%7}, {%8,%9}, {%0,%1,%2,%3};"    \
                 : "+f"((d)[0]), "+f"((d)[1]), "+f"((d)[2]), "+f"((d)[3])   \
                 : "r"((a)[0]), "r"((a)[1]), "r"((a)[2]), "r"((a)[3]),      \
                   "r"(b0v), "r"(b1v))

static __device__ __forceinline__ uint32_t pk(__half a, __half b) {
    return (uint32_t)__half_as_ushort(a) | ((uint32_t)__half_as_ushort(b) << 16);
}
static __device__ __forceinline__ uint32_t pkf(float a, float b) {
    __half2 h = __floats2half2_rn(a, b);
    return *(uint32_t*)&h;
}

// ---------------------------------------------------------------------------
// Preprocessing: round X to fp16, write A tile image (hi only).
// ---------------------------------------------------------------------------
__global__ void xsplit(const float* __restrict__ x)
{
    int i = blockIdx.x * 256 + threadIdx.x;      // 8-float chunk index
    int l = i * 8;
    int m = l >> 10, k = l & (D_ - 1);
    float4 v0 = ((const float4*)x)[2 * i];
    float4 v1 = ((const float4*)x)[2 * i + 1];
    uint4 h4 = make_uint4(pkf(v0.x, v0.y), pkf(v0.z, v0.w),
                          pkf(v1.x, v1.y), pkf(v1.z, v1.w));
    size_t base = ((size_t)(m >> 7) * 16 + (k >> 6)) * 16384;
    int r = m & 127, c = (k >> 3) & 7;
    *(uint4*)&g_aimg[base + r * 128 + SWZ(c, r)] = h4;
}

// ---------------------------------------------------------------------------
// Preprocessing: transpose W, fp16 round, write B tile image.
// ---------------------------------------------------------------------------
__global__ void wsplit(const float* __restrict__ Wq,
                       const float* __restrict__ Wk,
                       const float* __restrict__ Wv)
{
    __shared__ float t[32][33];
    const int z = blockIdx.z;
    const float* W = (z == 0) ? Wq : (z == 1) ? Wk : Wv;
    const int n  = blockIdx.x * 32 + threadIdx.x;
    const int k0 = blockIdx.y * 32;
    #pragma unroll
    for (int dy = 0; dy < 32; dy += 8) {
        int k = k0 + threadIdx.y + dy;
        t[threadIdx.y + dy][threadIdx.x] = W[(size_t)k * D_ + n];
    }
    __syncthreads();
    const int kk = k0 + threadIdx.x;
    #pragma unroll
    for (int dy = 0; dy < 32; dy += 8) {
        int nn = blockIdx.x * 32 + threadIdx.y + dy;
        float v = t[threadIdx.x][threadIdx.y + dy];
        size_t base = ((size_t)(z * 8 + (nn >> 7)) * 16 + (kk >> 6)) * 16384;
        int r = nn & 127, c = (kk >> 3) & 7, byb = (kk & 7) * 2;
        *(unsigned short*)&g_bimg[base + r * 128 + SWZ(c, r) + byb] =
            __half_as_ushort(__float2half_rn(v));
    }
}

// ---------------------------------------------------------------------------
// QKV GEMM: 1-term fp16 (Ah*Bh).  BK=64 chunks, 16 iters, 3x32KB stages.
// ---------------------------------------------------------------------------
#define NK     16
#define SMEM_G (1024 + 3 * 32768)

__global__ __launch_bounds__(256, 2) void qkv_gemm_mma()
{
    extern __shared__ char smem[];
    const uint32_t sb = s2u(smem);
    const int tid  = threadIdx.x;
    const int warp = tid >> 5;
    const int lane = tid & 31;
    const int wm   = warp & 1;
    const int wn   = warp >> 1;

    const int n0 = blockIdx.x * 128;
    const int m0 = blockIdx.y * 128;
    const int z  = blockIdx.z;

    if (tid == 0) {
        mbar_init(sb + 0, 1);
        mbar_init(sb + 8, 1);
        mbar_init(sb + 16, 1);
    }
    __syncthreads();

    const unsigned char* Asrc = g_aimg + (size_t)blockIdx.y * 16 * 16384;
    const unsigned char* Bsrc = g_bimg + (size_t)(z * 8 + blockIdx.x) * 16 * 16384;

    if (tid == 0) {
        #pragma unroll
        for (int s = 0; s < 3; s++) {
            mbar_expect_tx(sb + 8 * s, 32768);
            bulk_g2s(sb + 1024 + s * 32768,         Asrc + s * 16384, 16384, sb + 8 * s);
            bulk_g2s(sb + 1024 + s * 32768 + 16384, Bsrc + s * 16384, 16384, sb + 8 * s);
        }
    }

    float acc[4][4][4];
    #pragma unroll
    for (int mi = 0; mi < 4; mi++)
        #pragma unroll
        for (int ni = 0; ni < 4; ni++)
            #pragma unroll
            for (int r = 0; r < 4; r++) acc[mi][ni][r] = 0.f;

    int aRow[4];
    #pragma unroll
    for (int mi = 0; mi < 4; mi++) aRow[mi] = wm * 64 + mi * 16 + (lane & 15);
    const int aG = (lane >> 4);
    int bRow[2];
    #pragma unroll
    for (int p = 0; p < 2; p++) bRow[p] = wn * 32 + p * 16 + (lane & 7) + ((lane & 16) >> 1);
    const int bG = (lane >> 3) & 1;

    for (int i = 0; i < NK; i++) {
        const int s = i % 3;
        const uint32_t parity = (uint32_t)((i / 3) & 1);
        mbar_wait(sb + 8 * s, parity);

        const uint32_t aBase = sb + 1024 + s * 32768;
        const uint32_t bBase = aBase + 16384;

        #pragma unroll
        for (int kstep = 0; kstep < 4; kstep++) {
            const int g0 = kstep * 2;

            uint32_t ah[4][4], bh2[2][4];
            #pragma unroll
            for (int mi = 0; mi < 4; mi++) {
                int r = aRow[mi];
                uint32_t ad = aBase + r * 128 + (((g0 + aG) ^ (r & 7)) << 4);
                LDSM4(ah[mi][0], ah[mi][1], ah[mi][2], ah[mi][3], ad);
            }
            #pragma unroll
            for (int p = 0; p < 2; p++) {
                int r = bRow[p];
                uint32_t bd = bBase + r * 128 + (((g0 + bG) ^ (r & 7)) << 4);
                LDSM4(bh2[p][0], bh2[p][1], bh2[p][2], bh2[p][3], bd);
            }
            #pragma unroll
            for (int mi = 0; mi < 4; mi++)
                #pragma unroll
                for (int ni = 0; ni < 4; ni++)
                    MMA16816(acc[mi][ni], ah[mi], bh2[ni >> 1][(ni & 1) * 2], bh2[ni >> 1][(ni & 1) * 2 + 1]);
        }

        __syncthreads();
        const int nx = i + 3;
        if (nx < NK && tid == 0) {
            mbar_expect_tx(sb + 8 * s, 32768);
            bulk_g2s(aBase, Asrc + nx * 16384, 16384, sb + 8 * s);
            bulk_g2s(bBase, Bsrc + nx * 16384, 16384, sb + 8 * s);
        }
    }

    // epilogue: z=0 -> Q image (hi); z=1 -> Kh in KV image; z=2 -> V fp32
    #pragma unroll
    for (int mi = 0; mi < 4; mi++) {
        #pragma unroll
        for (int ni = 0; ni < 4; ni++) {
            int m = m0 + wm * 64 + mi * 16 + (lane >> 2);
            int n = n0 + wn * 32 + ni * 8 + ((lane & 3) << 1);
            int h  = n >> 6;
            int dh = n & (DH_ - 1);
            #pragma unroll
            for (int half = 0; half < 2; half++) {
                int mm = m + half * 8;
                int b  = mm >> 11;
                int sq = mm & (S_ - 1);
                float v0 = acc[mi][ni][half * 2];
                float v1 = acc[mi][ni][half * 2 + 1];
                if (z == 2) {
                    *(float2*)&g_v[(((size_t)(b * H_ + h) * S_ + sq) * DH_) + dh] =
                        make_float2(v0, v1);
                } else {
                    size_t bh = (size_t)b * H_ + h;
                    if (z == 0) {
                        size_t ob = (bh * 16 + (sq >> 7)) * 16384
                                  + (size_t)(sq & 127) * 128
                                  + SWZ(dh >> 3, sq & 127) + (dh & 7) * 2;
                        *(uint32_t*)&g_qimg[ob] = pkf(v0, v1);
                    } else {
                        size_t ob = (bh * 32 + (sq >> 6)) * (size_t)KVSTRIDE
                                  + (size_t)(sq & 63) * 128
                                  + SWZ(dh >> 3, sq & 63) + (dh & 7) * 2;
                        *(uint32_t*)&g_kvimg[ob] = pkf(v0, v1);
                    }
                }
            }
        }
    }
}

// ---------------------------------------------------------------------------
// V transpose: fp16 round, write Vh into KV image (+8192).
// ---------------------------------------------------------------------------
__global__ __launch_bounds__(256) void vtrans()
{
    __shared__ float t[64][65];
    const int b = blockIdx.z, h = blockIdx.y;
    const int s0 = blockIdx.x * 64;
    const int tid = threadIdx.x;
    const size_t bh = (size_t)b * H_ + h;
    const size_t base_in = (bh * S_ + s0) * DH_;
    #pragma unroll
    for (int i = 0; i < 16; i++) {
        int idx = tid + i * 256;
        int sl = idx >> 6, dh = idx & 63;
        t[sl][dh] = g_v[base_in + (size_t)sl * DH_ + dh];
    }
    __syncthreads();
    const size_t base = (bh * 32 + blockIdx.x) * (size_t)KVSTRIDE + 8192;
    #pragma unroll
    for (int i = 0; i < 8; i++) {
        int idx = (tid + i * 256) * 2;
        int dh = idx >> 6, sl = idx & 63;       // sl even
        uint32_t off = dh * 128 + SWZ((sl >> 3) & 7, dh) + (sl & 7) * 2;
        *(uint32_t*)&g_kvimg[base + off] = pkf(t[sl][dh], t[sl + 1][dh]);
    }
}

// ---------------------------------------------------------------------------
// Tensor-core flash attention: S 1-term, PV 1-term, frozen-max softmax.
// smem: mbars @ [0,1024); KV stages @1024+st*16K (3 stages); Q @1024+48K.
// ---------------------------------------------------------------------------
#define NKT    32
#define OFF_Q  (1024 + 3 * KVSTRIDE)
#define SMEM_A (OFF_Q + 16384)

__global__ __launch_bounds__(256, 2) void attn_mma(float* __restrict__ out)
{
    extern __shared__ char sm[];
    const uint32_t sb = s2u(sm);
    const int tid = threadIdx.x, warp = tid >> 5, lane = tid & 31;
    const int b = blockIdx.z, h = blockIdx.y, q0 = blockIdx.x * 128;
    const size_t bh = (size_t)(b * H_ + h);

    const unsigned char* Qsrc  = g_qimg + (bh * 16 + blockIdx.x) * 16384;
    const unsigned char* KVsrc = g_kvimg + bh * 32 * (size_t)KVSTRIDE;

    if (tid == 0) {
        mbar_init(sb + 0, 1);      // Q
        mbar_init(sb + 8, 1);      // KV stage 0
        mbar_init(sb + 16, 1);     // KV stage 1
        mbar_init(sb + 24, 1);     // KV stage 2
    }
    __syncthreads();

    if (tid == 0) {
        mbar_expect_tx(sb, 16384);
        bulk_g2s(sb + OFF_Q, Qsrc, 16384, sb);
        #pragma unroll
        for (int s = 0; s < 2; s++) {
            mbar_expect_tx(sb + 8 + 8 * s, KVSTRIDE);
            bulk_g2s(sb + 1024 + s * KVSTRIDE, KVsrc + (size_t)s * KVSTRIDE,
                     KVSTRIDE, sb + 8 + 8 * s);
        }
    }

    mbar_wait(sb, 0);

    uint32_t Qh[4][4];
    {
        const int ar = warp * 16 + (lane & 15);
        const int ag = lane >> 4;
        #pragma unroll
        for (int kc = 0; kc < 4; kc++) {
            uint32_t ad = sb + OFF_Q + ar * 128 + (((kc * 2 + ag) ^ (ar & 7)) << 4);
            LDSM4(Qh[kc][0], Qh[kc][1], Qh[kc][2], Qh[kc][3], ad);
        }
    }

    float o[8][4];
    #pragma unroll
    for (int j = 0; j < 8; j++)
        #pragma unroll
        for (int r = 0; r < 4; r++) o[j][r] = 0.f;
    float m0 = 0.f, m1 = 0.f, l0 = 0.f, l1 = 0.f;

    const int brb = (lane & 7) + ((lane & 16) >> 1);
    const int bg  = (lane >> 3) & 1;

    for (int t = 0; t < NKT; t++) {
        if (t + 2 < NKT && tid == 0) {
            const int st = (t + 2) % 3;
            mbar_expect_tx(sb + 8 + 8 * st, KVSTRIDE);
            bulk_g2s(sb + 1024 + st * KVSTRIDE, KVsrc + (size_t)(t + 2) * KVSTRIDE,
                     KVSTRIDE, sb + 8 + 8 * st);
        }
        mbar_wait(sb + 8 + 8 * (t % 3), (uint32_t)((t / 3) & 1));

        const uint32_t kvb = sb + 1024 + (t % 3) * KVSTRIDE;

        // ---- S = Qh Kh^T (1 term) ----
        float s[8][4];
        #pragma unroll
        for (int j = 0; j < 8; j++)
            #pragma unroll
            for (int r = 0; r < 4; r++) s[j][r] = 0.f;

        #pragma unroll
        for (int kc = 0; kc < 4; kc++) {
            const int g = kc * 2 + bg;
            uint32_t kf[4][4];
            #pragma unroll
            for (int nt = 0; nt < 4; nt++) {
                int r = nt * 16 + brb;
                uint32_t off = r * 128 + ((g ^ (r & 7)) << 4);
                LDSM4(kf[nt][0], kf[nt][1], kf[nt][2], kf[nt][3], kvb + off);
            }
            #pragma unroll
            for (int nt = 0; nt < 4; nt++)
                #pragma unroll
                for (int h2 = 0; h2 < 2; h2++) {
                    int ni = nt * 2 + h2;
                    MMA16816(s[ni], Qh[kc], kf[nt][h2 * 2], kf[nt][h2 * 2 + 1]);
                }
        }

        // ---- frozen-max softmax: max computed on tile 0 only ----
        if (t == 0) {
            float mt0 = -1e30f, mt1 = -1e30f;
            #pragma unroll
            for (int j = 0; j < 8; j++) {
                mt0 = fmaxf(mt0, fmaxf(s[j][0], s[j][1]));
                mt1 = fmaxf(mt1, fmaxf(s[j][2], s[j][3]));
            }
            mt0 *= 0.0625f; mt1 *= 0.0625f;
            mt0 = fmaxf(mt0, __shfl_xor_sync(0xFFFFFFFFu, mt0, 1));
            mt0 = fmaxf(mt0, __shfl_xor_sync(0xFFFFFFFFu, mt0, 2));
            mt1 = fmaxf(mt1, __shfl_xor_sync(0xFFFFFFFFu, mt1, 1));
            mt1 = fmaxf(mt1, __shfl_xor_sync(0xFFFFFFFFu, mt1, 2));
            m0 = mt0; m1 = mt1;
        }
        #pragma unroll
        for (int j = 0; j < 8; j++) {
            float p0 = __expf(fmaf(s[j][0], 0.0625f, -m0));
            float p1 = __expf(fmaf(s[j][1], 0.0625f, -m0));
            float p2 = __expf(fmaf(s[j][2], 0.0625f, -m1));
            float p3 = __expf(fmaf(s[j][3], 0.0625f, -m1));
            l0 += p0 + p1; l1 += p2 + p3;
            s[j][0] = p0; s[j][1] = p1; s[j][2] = p2; s[j][3] = p3;
        }

        // ---- O += Ph Vh (1 term) ----
        #pragma unroll
        for (int kc = 0; kc < 4; kc++) {
            const int g = kc * 2 + bg;
            uint32_t vh4[4][4];
            #pragma unroll
            for (int nt = 0; nt < 4; nt++) {
                int r = nt * 16 + brb;
                uint32_t off = r * 128 + ((g ^ (r & 7)) << 4);
                LDSM4(vh4[nt][0], vh4[nt][1], vh4[nt][2], vh4[nt][3], kvb + 8192 + off);
            }
            uint32_t Ahf[4];
            Ahf[0] = pkf(s[2 * kc][0],     s[2 * kc][1]);
            Ahf[1] = pkf(s[2 * kc][2],     s[2 * kc][3]);
            Ahf[2] = pkf(s[2 * kc + 1][0], s[2 * kc + 1][1]);
            Ahf[3] = pkf(s[2 * kc + 1][2], s[2 * kc + 1][3]);
            #pragma unroll
            for (int nt = 0; nt < 4; nt++)
                #pragma unroll
                for (int h2 = 0; h2 < 2; h2++) {
                    int ni = nt * 2 + h2;
                    MMA16816(o[ni], Ahf, vh4[nt][h2 * 2], vh4[nt][h2 * 2 + 1]);
                }
        }
        __syncthreads();
    }

    // ---- epilogue ----
    l0 += __shfl_xor_sync(0xFFFFFFFFu, l0, 1);
    l0 += __shfl_xor_sync(0xFFFFFFFFu, l0, 2);
    l1 += __shfl_xor_sync(0xFFFFFFFFu, l1, 1);
    l1 += __shfl_xor_sync(0xFFFFFFFFu, l1, 2);
    const float i0 = 1.0f / l0, i1 = 1.0f / l1;

    const int q = q0 + warp * 16 + (lane >> 2);
    float* op = out + ((size_t)b * S_ + q) * D_ + h * DH_;
    #pragma unroll
    for (int j = 0; j < 8; j++) {
        int dh = j * 8 + ((lane & 3) << 1);
        *(float2*)(op + dh)          = make_float2(o[j][0] * i0, o[j][1] * i0);
        *(float2*)(op + 8 * D_ + dh) = make_float2(o[j][2] * i1, o[j][3] * i1);
    }
}

// ---------------------------------------------------------------------------
// Launch
// ---------------------------------------------------------------------------
extern "C" void kernel_launch(void* const* d_in, const int* in_sizes, int n_in,
                              void* d_out, int out_size)
{
    const float* x  = (const float*)d_in[0];
    const float* wq = (const float*)d_in[1];
    const float* wk = (const float*)d_in[2];
    const float* wv = (const float*)d_in[3];
    float* out = (float*)d_out;

    static bool attr_set = false;
    if (!attr_set) {
        cudaFuncSetAttribute(qkv_gemm_mma,
                             cudaFuncAttributeMaxDynamicSharedMemorySize, SMEM_G);
        cudaFuncSetAttribute(attn_mma,
                             cudaFuncAttributeMaxDynamicSharedMemorySize, SMEM_A);
        attr_set = true;
    }

    xsplit<<<(M_ * D_ / 8) / 256, 256>>>(x);
    wsplit<<<dim3(32, 32, 3), dim3(32, 8)>>>(wq, wk, wv);
    qkv_gemm_mma<<<dim3(D_ / 128, M_ / 128, 3), 256, SMEM_G>>>();
    vtrans<<<dim3(S_ / 64, H_, B_), 256>>>();
    attn_mma<<<dim3(S_ / 128, H_, B_), 256, SMEM_A>>>(out);
}